// round 2
// baseline (speedup 1.0000x reference)
#include <cuda_runtime.h>
#include <cstdint>
#include <math.h>

#define Bc 64
#define Tc 512
#define Ec 512
#define Hc 512
#define Gc 1536            // 3*H
#define M_TOK (Bc*Tc)      // 32768 tokens
#define HY_OFF ((size_t)Bc*Tc*2*Hc)   // offset of hy in d_out
#define NBLK 128           // persistent grid size (64 j-chunks x 2 dirs)

// ---------------- device scratch (no allocation allowed) ----------------
__device__ float g_gx[(size_t)2*M_TOK*Gc];       // [dir][b*T+t][3H]
__device__ float g_h0out[(size_t)M_TOK*2*Hc];    // layer0 output [b][t][2H]
__device__ float g_h[2][2*Hc*Bc];                // [buf][dir][unit j][batch b]  (TRANSPOSED)

// barrier state
__device__ int g_bar_count = 0;
__device__ volatile int g_bar_gen = 0;

// packed fp32x2 fma (sm_103a)
#define FMA2(acc, a, b) asm("fma.rn.f32x2 %0, %1, %2, %0;" : "+l"(acc) : "l"(a), "l"(b))
#define PACK2(d, s)     asm("mov.b64 %0, {%1, %1};" : "=l"(d) : "f"(s))
#define UNPACK2(lo, hi, s) asm("mov.b64 {%0, %1}, %2;" : "=f"(lo), "=f"(hi) : "l"(s))

// ---------------- zero hidden state ----------------
__global__ void zero_h_kernel() {
    int i = blockIdx.x * blockDim.x + threadIdx.x;  // 2*H*B = 65536 threads
    g_h[0][i] = 0.0f;
}

// ---------------- gx GEMM:  C[dir][m][g] = A[m][:K] . W[dir][g][:K] + bias
// A row-major [M,K]; W row-major [2][1536][K]; 128x128 tile, 8x8/thread, f32x2 packed.
__global__ void __launch_bounds__(256, 2)
gemm_nt(const float* __restrict__ Ain,
        const float* __restrict__ W,
        const float* __restrict__ bias,
        int K, int use_h0)
{
    const int N = Gc;
    __shared__ float As[8][132];
    __shared__ float Bs[8][132];

    int dir = blockIdx.z;
    const float* A  = use_h0 ? g_h0out : Ain;
    const float* Bp = W + (size_t)dir * N * K;
    const float* bp = bias + dir * N;
    float* C = g_gx + (size_t)dir * M_TOK * N;

    int tid  = threadIdx.x;
    int lrow = tid >> 1;           // 0..127
    int kseg = (tid & 1) * 4;      // 0 or 4
    int ty = tid >> 4, tx = tid & 15;
    int m0 = blockIdx.y * 128, n0 = blockIdx.x * 128;

    const float* Aptr = A  + (size_t)(m0 + lrow) * K + kseg;
    const float* Bptr = Bp + (size_t)(n0 + lrow) * K + kseg;

    unsigned long long cc[8][4];
#pragma unroll
    for (int i = 0; i < 8; i++)
#pragma unroll
        for (int j = 0; j < 4; j++) cc[i][j] = 0ULL;

    for (int k0 = 0; k0 < K; k0 += 8) {
        float4 av = *(const float4*)(Aptr + k0);
        float4 bv = *(const float4*)(Bptr + k0);
        __syncthreads();
        As[kseg + 0][lrow] = av.x; As[kseg + 1][lrow] = av.y;
        As[kseg + 2][lrow] = av.z; As[kseg + 3][lrow] = av.w;
        Bs[kseg + 0][lrow] = bv.x; Bs[kseg + 1][lrow] = bv.y;
        Bs[kseg + 2][lrow] = bv.z; Bs[kseg + 3][lrow] = bv.w;
        __syncthreads();
#pragma unroll
        for (int kk = 0; kk < 8; kk++) {
            float4 a0 = *(const float4*)&As[kk][ty * 8];
            float4 a1 = *(const float4*)&As[kk][ty * 8 + 4];
            ulonglong2 bA = *(const ulonglong2*)&Bs[kk][tx * 8];
            ulonglong2 bB = *(const ulonglong2*)&Bs[kk][tx * 8 + 4];
            float av8[8] = {a0.x, a0.y, a0.z, a0.w, a1.x, a1.y, a1.z, a1.w};
#pragma unroll
            for (int i = 0; i < 8; i++) {
                unsigned long long a2;
                PACK2(a2, av8[i]);
                FMA2(cc[i][0], a2, bA.x);
                FMA2(cc[i][1], a2, bA.y);
                FMA2(cc[i][2], a2, bB.x);
                FMA2(cc[i][3], a2, bB.y);
            }
        }
    }

#pragma unroll
    for (int i = 0; i < 8; i++) {
        size_t rbase = (size_t)(m0 + ty * 8 + i) * N + n0 + tx * 8;
#pragma unroll
        for (int jp = 0; jp < 4; jp++) {
            float lo, hi;
            UNPACK2(lo, hi, cc[i][jp]);
            C[rbase + jp * 2 + 0] = lo + bp[n0 + tx * 8 + jp * 2 + 0];
            C[rbase + jp * 2 + 1] = hi + bp[n0 + tx * 8 + jp * 2 + 1];
        }
    }
}

// ---------------- grid barrier (all NBLK blocks co-resident) ----------------
__device__ __forceinline__ void grid_barrier(int* lgen) {
    __syncthreads();
    if (threadIdx.x == 0) {
        int g = *lgen;
        __threadfence();
        if (atomicAdd(&g_bar_count, 1) == NBLK - 1) {
            g_bar_count = 0;
            __threadfence();
            g_bar_gen = g + 1;
        } else {
            while (g_bar_gen == g) { }
        }
        *lgen = g + 1;
    }
    __syncthreads();
}

// ---------------- persistent recurrence: all 512 steps in one launch ----------------
// Grid (64, 1, 2), 128 threads. Block owns units [j0, j0+8), all 64 batches.
// Thread (jl = tid/16, bg = tid%16) -> unit j0+jl, batches 4*bg..4*bg+3.
// h state is TRANSPOSED in global: g_h[buf][dir][j][b].
// Dyn smem: sw2[24][516] float2 (weights duplicated for f32x2)  +  sh[64][68] float.
__global__ void __launch_bounds__(128, 1)
gru_persist_kernel(const float* __restrict__ w_hh,   // [2][3H][H]
                   const float* __restrict__ b_hh,   // [2][3H]
                   float* __restrict__ out_l1,
                   int layer)
{
    extern __shared__ char smem_raw[];
    float2* sw2 = (float2*)smem_raw;                       // [24][516]
    float*  sh  = (float*)(smem_raw + 24 * 516 * sizeof(float2));  // [64][68]

    int dir = blockIdx.z;
    int j0  = blockIdx.x * 8;
    int tid = threadIdx.x;
    int jl  = tid >> 4;     // 0..7
    int bg  = tid & 15;     // 0..15
    int j   = j0 + jl;

    const float* W = w_hh + (size_t)dir * Gc * Hc;
    const float* gx = g_gx + (size_t)dir * M_TOK * Gc;
    float* hs = (layer == 0) ? g_h0out : out_l1;

    // preload weights once: rows (gate g, unit jl) -> duplicated float2
    for (int idx = tid; idx < 24 * 512; idx += 128) {
        int r = idx >> 9;          // 0..23 : r = g*8 + jj
        int k = idx & 511;
        int gg = r >> 3, jj = r & 7;
        float w = W[(size_t)(gg * Hc + j0 + jj) * Hc + k];
        sw2[r * 516 + k] = make_float2(w, w);
    }

    float br = b_hh[dir * Gc + j];
    float bz = b_hh[dir * Gc + Hc + j];
    float bn = b_hh[dir * Gc + 2 * Hc + j];

    int lgen = g_bar_gen;
    __syncthreads();   // weights visible

    for (int s = 0; s < Tc; s++) {
        int bufsel = s & 1;
        int t = dir ? (Tc - 1 - s) : s;
        const float* hin  = &g_h[bufsel][dir * Hc * Bc];
        float*       hout = &g_h[bufsel ^ 1][dir * Hc * Bc];

        unsigned long long ar01 = 0, ar23 = 0, az01 = 0, az23 = 0, an01 = 0, an23 = 0;

        for (int k0 = 0; k0 < Hc; k0 += 64) {
            __syncthreads();
            // stage h chunk: rows = hidden unit k, cols = batch (conflict-free STS.128)
#pragma unroll
            for (int p = 0; p < 8; p++) {
                int idx = tid + p * 128;
                int kr = idx >> 4;      // 0..63
                int b4 = idx & 15;
                float4 v = __ldcg((const float4*)&hin[(k0 + kr) * Bc + b4 * 4]);
                *(float4*)&sh[kr * 68 + b4 * 4] = v;
            }
            __syncthreads();

            const unsigned long long* wr = (const unsigned long long*)sw2 + (0 * 8 + jl) * 516 + k0;
            const unsigned long long* wz = (const unsigned long long*)sw2 + (1 * 8 + jl) * 516 + k0;
            const unsigned long long* wn = (const unsigned long long*)sw2 + (2 * 8 + jl) * 516 + k0;
#pragma unroll 8
            for (int k = 0; k < 64; k++) {
                ulonglong2 hv = *(const ulonglong2*)&sh[k * 68 + bg * 4];
                unsigned long long w;
                w = wr[k]; FMA2(ar01, hv.x, w); FMA2(ar23, hv.y, w);
                w = wz[k]; FMA2(az01, hv.x, w); FMA2(az23, hv.y, w);
                w = wn[k]; FMA2(an01, hv.x, w); FMA2(an23, hv.y, w);
            }
        }

        float ar[4], az[4], an[4];
        UNPACK2(ar[0], ar[1], ar01); UNPACK2(ar[2], ar[3], ar23);
        UNPACK2(az[0], az[1], az01); UNPACK2(az[2], az[3], az23);
        UNPACK2(an[0], an[1], an01); UNPACK2(an[2], an[3], an23);

        float4 hp4 = __ldcg((const float4*)&hin[j * Bc + bg * 4]);
        float hp[4] = {hp4.x, hp4.y, hp4.z, hp4.w};
        float hn[4];

#pragma unroll
        for (int q = 0; q < 4; q++) {
            int b = bg * 4 + q;
            size_t gbase = ((size_t)b * Tc + t) * Gc;
            float gr = gx[gbase + j];
            float gz = gx[gbase + Hc + j];
            float gn = gx[gbase + 2 * Hc + j];
            float rr = 1.0f / (1.0f + expf(-(gr + ar[q] + br)));
            float zz = 1.0f / (1.0f + expf(-(gz + az[q] + bz)));
            float nn = tanhf(gn + rr * (an[q] + bn));
            hn[q] = (1.0f - zz) * nn + zz * hp[q];
            hs[((size_t)b * Tc + t) * (2 * Hc) + dir * Hc + j] = hn[q];
        }
        *(float4*)&hout[j * Bc + bg * 4] = make_float4(hn[0], hn[1], hn[2], hn[3]);

        if (s != Tc - 1) grid_barrier(&lgen);
    }
}

// ---------------- copy final hidden states (transposed h -> [dir][b][H]) ----------------
__global__ void hy_copy_kernel(float* __restrict__ d_out, int layer) {
    int i = blockIdx.x * blockDim.x + threadIdx.x;   // 0 .. 2*B*H-1
    int dir = i >> 15;             // /(B*H)
    int rem = i & 32767;
    int b = rem >> 9;              // /H
    int jj = rem & 511;
    // final h lives in buffer 0 after 512 steps
    d_out[HY_OFF + (size_t)(2 * layer + dir) * Bc * Hc + (size_t)b * Hc + jj] =
        g_h[0][dir * Hc * Bc + jj * Bc + b];
}

// ---------------- launch ----------------
extern "C" void kernel_launch(void* const* d_in, const int* in_sizes, int n_in,
                              void* d_out, int out_size)
{
    const float* xs    = (const float*)d_in[0];
    const float* w_ih0 = (const float*)d_in[1];
    const float* w_hh0 = (const float*)d_in[2];
    const float* b_ih0 = (const float*)d_in[3];
    const float* b_hh0 = (const float*)d_in[4];
    const float* w_ih1 = (const float*)d_in[5];
    const float* w_hh1 = (const float*)d_in[6];
    const float* b_ih1 = (const float*)d_in[7];
    const float* b_hh1 = (const float*)d_in[8];
    float* out = (float*)d_out;

    const int PERSIST_SMEM = 24 * 516 * (int)sizeof(float2) + 64 * 68 * (int)sizeof(float); // 116480
    cudaFuncSetAttribute(gru_persist_kernel,
                         cudaFuncAttributeMaxDynamicSharedMemorySize, PERSIST_SMEM);

    dim3 gemm_grid(Gc / 128, M_TOK / 128, 2);   // (12, 256, 2)
    dim3 persist_grid(Hc / 8, 1, 2);            // (64, 1, 2) = 128 blocks

    // ---- layer 0 ----
    gemm_nt<<<gemm_grid, 256>>>(xs, w_ih0, b_ih0, Ec, 0);
    zero_h_kernel<<<(2 * Hc * Bc) / 256, 256>>>();
    gru_persist_kernel<<<persist_grid, 128, PERSIST_SMEM>>>(w_hh0, b_hh0, out, 0);
    hy_copy_kernel<<<(2 * Bc * Hc) / 256, 256>>>(out, 0);

    // ---- layer 1 ----
    gemm_nt<<<gemm_grid, 256>>>(xs /*unused*/, w_ih1, b_ih1, 2 * Hc, 1);
    zero_h_kernel<<<(2 * Hc * Bc) / 256, 256>>>();
    gru_persist_kernel<<<persist_grid, 128, PERSIST_SMEM>>>(w_hh1, b_hh1, out, 1);
    hy_copy_kernel<<<(2 * Bc * Hc) / 256, 256>>>(out, 1);
}

// round 4
// speedup vs baseline: 1.1970x; 1.1970x over previous
#include <cuda_runtime.h>
#include <cuda_bf16.h>
#include <cstdint>
#include <math.h>

#define Bc 64
#define Tc 512
#define Ec 512
#define Hc 512
#define Gc 1536            // 3*H
#define M_TOK (Bc*Tc)      // 32768 tokens
#define HY_OFF ((size_t)Bc*Tc*2*Hc)
#define NBLK 128

// ---------------- device scratch ----------------
__device__ float g_gx[(size_t)2*M_TOK*Gc];       // [dir][b*T+t][3H]
__device__ float g_h0out[(size_t)M_TOK*2*Hc];    // layer0 output [b][t][2H]
__device__ float g_h[2][2*Hc*Bc];                // [buf][dir][j][b]

// bf16 split operands for tensor-core GEMMs
__device__ __nv_bfloat16 g_xs_hi[(size_t)M_TOK*Ec],  g_xs_lo[(size_t)M_TOK*Ec];
__device__ __nv_bfloat16 g_h0_hi[(size_t)M_TOK*2*Hc], g_h0_lo[(size_t)M_TOK*2*Hc];
__device__ __nv_bfloat16 g_w0_hi[(size_t)2*Gc*Ec],   g_w0_lo[(size_t)2*Gc*Ec];
__device__ __nv_bfloat16 g_w1_hi[(size_t)2*Gc*2*Hc], g_w1_lo[(size_t)2*Gc*2*Hc];

// barrier state
__device__ int g_bar_count = 0;
__device__ volatile int g_bar_gen = 0;

// packed fp32x2 fma (sm_103a)
#define FMA2(acc, a, b) asm("fma.rn.f32x2 %0, %1, %2, %0;" : "+l"(acc) : "l"(a), "l"(b))
#define UNPACK2(lo, hi, s) asm("mov.b64 {%0, %1}, %2;" : "=f"(lo), "=f"(hi) : "l"(s))

// warp-mma helpers (base PTX, no 'a'-features)
#define LDSM4(r0, r1, r2, r3, addr) \
    asm volatile("ldmatrix.sync.aligned.m8n8.x4.shared.b16 {%0,%1,%2,%3}, [%4];" \
                 : "=r"(r0), "=r"(r1), "=r"(r2), "=r"(r3) : "r"(addr))

#define MMA16816(d, a, b0, b1) \
    asm volatile("mma.sync.aligned.m16n8k16.row.col.f32.bf16.bf16.f32 " \
                 "{%0,%1,%2,%3}, {%4,%5,%6,%7}, {%8,%9}, {%0,%1,%2,%3};" \
                 : "+f"(d[0]), "+f"(d[1]), "+f"(d[2]), "+f"(d[3]) \
                 : "r"(a[0]), "r"(a[1]), "r"(a[2]), "r"(a[3]), "r"(b0), "r"(b1))

__device__ __forceinline__ uint32_t smem_u32(const void* p) {
    uint32_t a;
    asm("{ .reg .u64 t; cvta.to.shared.u64 t, %1; cvt.u32.u64 %0, t; }" : "=r"(a) : "l"(p));
    return a;
}

// ---------------- bf16 split prep ----------------
__global__ void split_bf16_kernel(const float* __restrict__ src,
                                  __nv_bfloat16* __restrict__ hi,
                                  __nv_bfloat16* __restrict__ lo, size_t n) {
    size_t i = (size_t)blockIdx.x * blockDim.x + threadIdx.x;
    if (i >= n) return;
    float a = src[i];
    __nv_bfloat16 h = __float2bfloat16(a);
    hi[i] = h;
    lo[i] = __float2bfloat16(a - __bfloat162float(h));
}

// ---------------- zero hidden state ----------------
__global__ void zero_h_kernel() {
    int i = blockIdx.x * blockDim.x + threadIdx.x;
    g_h[0][i] = 0.0f;
}

// ---------------- tensor-core gx GEMM (warp mma.sync, bf16 3-product split) ----
// C[dir][m][g] = A[m][:K] . W[dir][g][:K] + bias[dir][g]
// Block tile 128(M)x128(N), 256 threads = 8 warps (2 warps N x 4 warps M),
// warp tile 32(M)x64(N). K staged in 32-wide chunks, smem pitch 40 bf16.
#define KC 32
#define PITCH 40

__global__ void __launch_bounds__(256, 2)
gemm_mma(const __nv_bfloat16* __restrict__ Ahi, const __nv_bfloat16* __restrict__ Alo,
         const __nv_bfloat16* __restrict__ Whi, const __nv_bfloat16* __restrict__ Wlo,
         const float* __restrict__ bias, int K)
{
    __shared__ __nv_bfloat16 sAhi[128 * PITCH], sAlo[128 * PITCH];
    __shared__ __nv_bfloat16 sBhi[128 * PITCH], sBlo[128 * PITCH];

    int tid  = threadIdx.x;
    int wid  = tid >> 5, lane = tid & 31;
    int dir  = blockIdx.z;
    int n0   = blockIdx.x * 128;
    int m0   = blockIdx.y * 128;
    int wm   = wid >> 1;          // 0..3  -> m offset 32*wm
    int wn   = wid & 1;           // 0..1  -> n offset 64*wn

    const __nv_bfloat16* bhi = Whi + (size_t)dir * Gc * K;
    const __nv_bfloat16* blo = Wlo + (size_t)dir * Gc * K;
    float* C = g_gx + (size_t)dir * M_TOK * Gc;
    const float* bp = bias + dir * Gc;

    float acc[2][8][4];
#pragma unroll
    for (int i = 0; i < 2; i++)
#pragma unroll
        for (int j = 0; j < 8; j++)
#pragma unroll
            for (int q = 0; q < 4; q++) acc[i][j][q] = 0.0f;

    uint32_t uAhi = smem_u32(sAhi), uAlo = smem_u32(sAlo);
    uint32_t uBhi = smem_u32(sBhi), uBlo = smem_u32(sBlo);

    // ldmatrix lane addressing (bytes)
    int a_row = (lane & 15);
    int a_col = (lane >> 4) * 8;
    int b_row = (lane & 7) + ((lane >> 4) & 1) * 8;
    int b_col = ((lane >> 3) & 1) * 8;

    const int nchunks = K / KC;
    for (int c = 0; c < nchunks; c++) {
        int k0 = c * KC;
        __syncthreads();
        // stage 4 tiles: 128 rows x 32 bf16 each (2 uint4 per thread per tile)
#pragma unroll
        for (int p = 0; p < 2; p++) {
            int idx = p * 256 + tid;          // 0..511
            int r   = idx >> 2;
            int c4  = idx & 3;
            size_t ga = (size_t)(m0 + r) * K + k0 + c4 * 8;
            size_t gb = (size_t)(n0 + r) * K + k0 + c4 * 8;
            int so = r * PITCH + c4 * 8;
            *(uint4*)&sAhi[so] = *(const uint4*)(Ahi + ga);
            *(uint4*)&sAlo[so] = *(const uint4*)(Alo + ga);
            *(uint4*)&sBhi[so] = *(const uint4*)(bhi + gb);
            *(uint4*)&sBlo[so] = *(const uint4*)(blo + gb);
        }
        __syncthreads();

#pragma unroll
        for (int kk = 0; kk < 2; kk++) {
            int k16 = kk * 16;
            uint32_t ahi[2][4], alo[2][4];
#pragma unroll
            for (int mt = 0; mt < 2; mt++) {
                uint32_t off = 2u * ((wm * 32 + mt * 16 + a_row) * PITCH + k16 + a_col);
                LDSM4(ahi[mt][0], ahi[mt][1], ahi[mt][2], ahi[mt][3], uAhi + off);
                LDSM4(alo[mt][0], alo[mt][1], alo[mt][2], alo[mt][3], uAlo + off);
            }
#pragma unroll
            for (int np = 0; np < 4; np++) {
                uint32_t off = 2u * ((wn * 64 + np * 16 + b_row) * PITCH + k16 + b_col);
                uint32_t bh0, bh1, bh2, bh3, bl0, bl1, bl2, bl3;
                LDSM4(bh0, bh1, bh2, bh3, uBhi + off);
                LDSM4(bl0, bl1, bl2, bl3, uBlo + off);
#pragma unroll
                for (int mt = 0; mt < 2; mt++) {
                    MMA16816(acc[mt][np * 2 + 0], ahi[mt], bh0, bh1);
                    MMA16816(acc[mt][np * 2 + 0], ahi[mt], bl0, bl1);
                    MMA16816(acc[mt][np * 2 + 0], alo[mt], bh0, bh1);
                    MMA16816(acc[mt][np * 2 + 1], ahi[mt], bh2, bh3);
                    MMA16816(acc[mt][np * 2 + 1], ahi[mt], bl2, bl3);
                    MMA16816(acc[mt][np * 2 + 1], alo[mt], bh2, bh3);
                }
            }
        }
    }

    // epilogue: acc layout per frag: lane -> row = lane>>2 (+8), col pair = 2*(lane&3)
#pragma unroll
    for (int mt = 0; mt < 2; mt++) {
#pragma unroll
        for (int nt = 0; nt < 8; nt++) {
            int row = m0 + wm * 32 + mt * 16 + (lane >> 2);
            int col = n0 + wn * 64 + nt * 8 + (lane & 3) * 2;
            float b0 = bp[col], b1 = bp[col + 1];
            float2 v0 = make_float2(acc[mt][nt][0] + b0, acc[mt][nt][1] + b1);
            float2 v1 = make_float2(acc[mt][nt][2] + b0, acc[mt][nt][3] + b1);
            *(float2*)&C[(size_t)row * Gc + col]       = v0;
            *(float2*)&C[(size_t)(row + 8) * Gc + col] = v1;
        }
    }
}

// ---------------- grid barrier ----------------
__device__ __forceinline__ void grid_barrier(int* lgen) {
    __syncthreads();
    if (threadIdx.x == 0) {
        int g = *lgen;
        __threadfence();
        if (atomicAdd(&g_bar_count, 1) == NBLK - 1) {
            g_bar_count = 0;
            __threadfence();
            g_bar_gen = g + 1;
        } else {
            while (g_bar_gen == g) { }
        }
        *lgen = g + 1;
    }
    __syncthreads();
}

// ---------------- persistent recurrence (unchanged from passing R2) ----------------
__global__ void __launch_bounds__(128, 1)
gru_persist_kernel(const float* __restrict__ w_hh,
                   const float* __restrict__ b_hh,
                   float* __restrict__ out_l1,
                   int layer)
{
    extern __shared__ char smem_raw[];
    float2* sw2 = (float2*)smem_raw;                       // [24][516]
    float*  sh  = (float*)(smem_raw + 24 * 516 * sizeof(float2));  // [64][68]

    int dir = blockIdx.z;
    int j0  = blockIdx.x * 8;
    int tid = threadIdx.x;
    int jl  = tid >> 4;
    int bg  = tid & 15;
    int j   = j0 + jl;

    const float* W = w_hh + (size_t)dir * Gc * Hc;
    const float* gx = g_gx + (size_t)dir * M_TOK * Gc;
    float* hs = (layer == 0) ? g_h0out : out_l1;

    for (int idx = tid; idx < 24 * 512; idx += 128) {
        int r = idx >> 9;
        int k = idx & 511;
        int gg = r >> 3, jj = r & 7;
        float w = W[(size_t)(gg * Hc + j0 + jj) * Hc + k];
        sw2[r * 516 + k] = make_float2(w, w);
    }

    float br = b_hh[dir * Gc + j];
    float bz = b_hh[dir * Gc + Hc + j];
    float bn = b_hh[dir * Gc + 2 * Hc + j];

    int lgen = g_bar_gen;
    __syncthreads();

    for (int s = 0; s < Tc; s++) {
        int bufsel = s & 1;
        int t = dir ? (Tc - 1 - s) : s;
        const float* hin  = &g_h[bufsel][dir * Hc * Bc];
        float*       hout = &g_h[bufsel ^ 1][dir * Hc * Bc];

        unsigned long long ar01 = 0, ar23 = 0, az01 = 0, az23 = 0, an01 = 0, an23 = 0;

        for (int k0 = 0; k0 < Hc; k0 += 64) {
            __syncthreads();
#pragma unroll
            for (int p = 0; p < 8; p++) {
                int idx = tid + p * 128;
                int kr = idx >> 4;
                int b4 = idx & 15;
                float4 v = __ldcg((const float4*)&hin[(k0 + kr) * Bc + b4 * 4]);
                *(float4*)&sh[kr * 68 + b4 * 4] = v;
            }
            __syncthreads();

            const unsigned long long* wr = (const unsigned long long*)sw2 + (0 * 8 + jl) * 516 + k0;
            const unsigned long long* wz = (const unsigned long long*)sw2 + (1 * 8 + jl) * 516 + k0;
            const unsigned long long* wn = (const unsigned long long*)sw2 + (2 * 8 + jl) * 516 + k0;
#pragma unroll 8
            for (int k = 0; k < 64; k++) {
                ulonglong2 hv = *(const ulonglong2*)&sh[k * 68 + bg * 4];
                unsigned long long w;
                w = wr[k]; FMA2(ar01, hv.x, w); FMA2(ar23, hv.y, w);
                w = wz[k]; FMA2(az01, hv.x, w); FMA2(az23, hv.y, w);
                w = wn[k]; FMA2(an01, hv.x, w); FMA2(an23, hv.y, w);
            }
        }

        float ar[4], az[4], an[4];
        UNPACK2(ar[0], ar[1], ar01); UNPACK2(ar[2], ar[3], ar23);
        UNPACK2(az[0], az[1], az01); UNPACK2(az[2], az[3], az23);
        UNPACK2(an[0], an[1], an01); UNPACK2(an[2], an[3], an23);

        float4 hp4 = __ldcg((const float4*)&hin[j * Bc + bg * 4]);
        float hp[4] = {hp4.x, hp4.y, hp4.z, hp4.w};
        float hn[4];

#pragma unroll
        for (int q = 0; q < 4; q++) {
            int b = bg * 4 + q;
            size_t gbase = ((size_t)b * Tc + t) * Gc;
            float gr = gx[gbase + j];
            float gz = gx[gbase + Hc + j];
            float gn = gx[gbase + 2 * Hc + j];
            float rr = 1.0f / (1.0f + expf(-(gr + ar[q] + br)));
            float zz = 1.0f / (1.0f + expf(-(gz + az[q] + bz)));
            float nn = tanhf(gn + rr * (an[q] + bn));
            hn[q] = (1.0f - zz) * nn + zz * hp[q];
            hs[((size_t)b * Tc + t) * (2 * Hc) + dir * Hc + j] = hn[q];
        }
        *(float4*)&hout[j * Bc + bg * 4] = make_float4(hn[0], hn[1], hn[2], hn[3]);

        if (s != Tc - 1) grid_barrier(&lgen);
    }
}

// ---------------- copy final hidden states ----------------
__global__ void hy_copy_kernel(float* __restrict__ d_out, int layer) {
    int i = blockIdx.x * blockDim.x + threadIdx.x;
    int dir = i >> 15;
    int rem = i & 32767;
    int b = rem >> 9;
    int jj = rem & 511;
    d_out[HY_OFF + (size_t)(2 * layer + dir) * Bc * Hc + (size_t)b * Hc + jj] =
        g_h[0][dir * Hc * Bc + jj * Bc + b];
}

// ---------------- launch ----------------
extern "C" void kernel_launch(void* const* d_in, const int* in_sizes, int n_in,
                              void* d_out, int out_size)
{
    const float* xs    = (const float*)d_in[0];
    const float* w_ih0 = (const float*)d_in[1];
    const float* w_hh0 = (const float*)d_in[2];
    const float* b_ih0 = (const float*)d_in[3];
    const float* b_hh0 = (const float*)d_in[4];
    const float* w_ih1 = (const float*)d_in[5];
    const float* w_hh1 = (const float*)d_in[6];
    const float* b_ih1 = (const float*)d_in[7];
    const float* b_hh1 = (const float*)d_in[8];
    float* out = (float*)d_out;

    const int PERSIST_SMEM = 24 * 516 * (int)sizeof(float2) + 64 * 68 * (int)sizeof(float);
    cudaFuncSetAttribute(gru_persist_kernel,
                         cudaFuncAttributeMaxDynamicSharedMemorySize, PERSIST_SMEM);

    __nv_bfloat16 *xs_hi, *xs_lo, *h0_hi, *h0_lo, *w0_hi, *w0_lo, *w1_hi, *w1_lo;
    cudaGetSymbolAddress((void**)&xs_hi, g_xs_hi);
    cudaGetSymbolAddress((void**)&xs_lo, g_xs_lo);
    cudaGetSymbolAddress((void**)&h0_hi, g_h0_hi);
    cudaGetSymbolAddress((void**)&h0_lo, g_h0_lo);
    cudaGetSymbolAddress((void**)&w0_hi, g_w0_hi);
    cudaGetSymbolAddress((void**)&w0_lo, g_w0_lo);
    cudaGetSymbolAddress((void**)&w1_hi, g_w1_hi);
    cudaGetSymbolAddress((void**)&w1_lo, g_w1_lo);
    float* h0out;
    cudaGetSymbolAddress((void**)&h0out, g_h0out);

    dim3 gemm_grid(Gc / 128, M_TOK / 128, 2);   // (12, 256, 2)
    dim3 persist_grid(Hc / 8, 1, 2);            // 128 blocks

    size_t n_w0 = (size_t)2 * Gc * Ec;
    size_t n_w1 = (size_t)2 * Gc * 2 * Hc;
    size_t n_xs = (size_t)M_TOK * Ec;
    size_t n_h0 = (size_t)M_TOK * 2 * Hc;

    split_bf16_kernel<<<(unsigned)((n_w0 + 255) / 256), 256>>>(w_ih0, w0_hi, w0_lo, n_w0);
    split_bf16_kernel<<<(unsigned)((n_w1 + 255) / 256), 256>>>(w_ih1, w1_hi, w1_lo, n_w1);
    split_bf16_kernel<<<(unsigned)((n_xs + 255) / 256), 256>>>(xs, xs_hi, xs_lo, n_xs);

    // ---- layer 0 ----
    gemm_mma<<<gemm_grid, 256>>>(xs_hi, xs_lo, w0_hi, w0_lo, b_ih0, Ec);
    zero_h_kernel<<<(2 * Hc * Bc) / 256, 256>>>();
    gru_persist_kernel<<<persist_grid, 128, PERSIST_SMEM>>>(w_hh0, b_hh0, out, 0);
    hy_copy_kernel<<<(2 * Bc * Hc) / 256, 256>>>(out, 0);

    // ---- layer 1 ----
    split_bf16_kernel<<<(unsigned)((n_h0 + 255) / 256), 256>>>(h0out, h0_hi, h0_lo, n_h0);
    gemm_mma<<<gemm_grid, 256>>>(h0_hi, h0_lo, w1_hi, w1_lo, b_ih1, 2 * Hc);
    zero_h_kernel<<<(2 * Hc * Bc) / 256, 256>>>();
    gru_persist_kernel<<<persist_grid, 128, PERSIST_SMEM>>>(w_hh1, b_hh1, out, 1);
    hy_copy_kernel<<<(2 * Bc * Hc) / 256, 256>>>(out, 1);
}

// round 5
// speedup vs baseline: 2.1963x; 1.8349x over previous
#include <cuda_runtime.h>
#include <cuda_bf16.h>
#include <cstdint>
#include <math.h>

#define Bc 64
#define Tc 512
#define Ec 512
#define Hc 512
#define Gc 1536            // 3*H
#define M_TOK (Bc*Tc)      // 32768 tokens
#define HY_OFF ((size_t)Bc*Tc*2*Hc)
#define NBLK 128

// ---------------- device scratch ----------------
__device__ float g_gx[(size_t)2*M_TOK*Gc];       // [dir][b*T+t][3H]
__device__ float g_h0out[(size_t)M_TOK*2*Hc];    // layer0 output [b][t][2H]

// h state as bf16 hi/lo split, layout [buf][dir][batch b][hidden j]
__device__ __nv_bfloat16 g_hAhi[2][2*Bc*Hc];
__device__ __nv_bfloat16 g_hAlo[2][2*Bc*Hc];

// bf16 split operands for gx GEMMs
__device__ __nv_bfloat16 g_xs_hi[(size_t)M_TOK*Ec],  g_xs_lo[(size_t)M_TOK*Ec];
__device__ __nv_bfloat16 g_h0_hi[(size_t)M_TOK*2*Hc], g_h0_lo[(size_t)M_TOK*2*Hc];
__device__ __nv_bfloat16 g_w0_hi[(size_t)2*Gc*Ec],   g_w0_lo[(size_t)2*Gc*Ec];
__device__ __nv_bfloat16 g_w1_hi[(size_t)2*Gc*2*Hc], g_w1_lo[(size_t)2*Gc*2*Hc];

// barrier state
__device__ int g_bar_count = 0;
__device__ volatile int g_bar_gen = 0;

// warp-mma helpers (base PTX, no 'a'-features)
#define LDSM4(r0, r1, r2, r3, addr) \
    asm volatile("ldmatrix.sync.aligned.m8n8.x4.shared.b16 {%0,%1,%2,%3}, [%4];" \
                 : "=r"(r0), "=r"(r1), "=r"(r2), "=r"(r3) : "r"(addr))

#define MMA16816(d, a, b0, b1) \
    asm volatile("mma.sync.aligned.m16n8k16.row.col.f32.bf16.bf16.f32 " \
                 "{%0,%1,%2,%3}, {%4,%5,%6,%7}, {%8,%9}, {%0,%1,%2,%3};" \
                 : "+f"(d[0]), "+f"(d[1]), "+f"(d[2]), "+f"(d[3]) \
                 : "r"(a[0]), "r"(a[1]), "r"(a[2]), "r"(a[3]), "r"(b0), "r"(b1))

__device__ __forceinline__ uint32_t smem_u32(const void* p) {
    uint32_t a;
    asm("{ .reg .u64 t; cvta.to.shared.u64 t, %1; cvt.u32.u64 %0, t; }" : "=r"(a) : "l"(p));
    return a;
}

// ---------------- bf16 split prep ----------------
__global__ void split_bf16_kernel(const float* __restrict__ src,
                                  __nv_bfloat16* __restrict__ hi,
                                  __nv_bfloat16* __restrict__ lo, size_t n) {
    size_t i = (size_t)blockIdx.x * blockDim.x + threadIdx.x;
    if (i >= n) return;
    float a = src[i];
    __nv_bfloat16 h = __float2bfloat16(a);
    hi[i] = h;
    lo[i] = __float2bfloat16(a - __bfloat162float(h));
}

// ---------------- zero hidden state (buf 0, both splits) ----------------
__global__ void zero_h_kernel() {
    int i = blockIdx.x * blockDim.x + threadIdx.x;   // 2*B*H = 65536
    g_hAhi[0][i] = __float2bfloat16(0.0f);
    g_hAlo[0][i] = __float2bfloat16(0.0f);
}

// ---------------- tensor-core gx GEMM (unchanged from passing R4) ----------
#define KC 32
#define PITCH 40

__global__ void __launch_bounds__(256, 2)
gemm_mma(const __nv_bfloat16* __restrict__ Ahi, const __nv_bfloat16* __restrict__ Alo,
         const __nv_bfloat16* __restrict__ Whi, const __nv_bfloat16* __restrict__ Wlo,
         const float* __restrict__ bias, int K)
{
    __shared__ __nv_bfloat16 sAhi[128 * PITCH], sAlo[128 * PITCH];
    __shared__ __nv_bfloat16 sBhi[128 * PITCH], sBlo[128 * PITCH];

    int tid  = threadIdx.x;
    int wid  = tid >> 5, lane = tid & 31;
    int dir  = blockIdx.z;
    int n0   = blockIdx.x * 128;
    int m0   = blockIdx.y * 128;
    int wm   = wid >> 1;
    int wn   = wid & 1;

    const __nv_bfloat16* bhi = Whi + (size_t)dir * Gc * K;
    const __nv_bfloat16* blo = Wlo + (size_t)dir * Gc * K;
    float* C = g_gx + (size_t)dir * M_TOK * Gc;
    const float* bp = bias + dir * Gc;

    float acc[2][8][4];
#pragma unroll
    for (int i = 0; i < 2; i++)
#pragma unroll
        for (int j = 0; j < 8; j++)
#pragma unroll
            for (int q = 0; q < 4; q++) acc[i][j][q] = 0.0f;

    uint32_t uAhi = smem_u32(sAhi), uAlo = smem_u32(sAlo);
    uint32_t uBhi = smem_u32(sBhi), uBlo = smem_u32(sBlo);

    int a_row = (lane & 15);
    int a_col = (lane >> 4) * 8;
    int b_row = (lane & 7) + ((lane >> 4) & 1) * 8;
    int b_col = ((lane >> 3) & 1) * 8;

    const int nchunks = K / KC;
    for (int c = 0; c < nchunks; c++) {
        int k0 = c * KC;
        __syncthreads();
#pragma unroll
        for (int p = 0; p < 2; p++) {
            int idx = p * 256 + tid;
            int r   = idx >> 2;
            int c4  = idx & 3;
            size_t ga = (size_t)(m0 + r) * K + k0 + c4 * 8;
            size_t gb = (size_t)(n0 + r) * K + k0 + c4 * 8;
            int so = r * PITCH + c4 * 8;
            *(uint4*)&sAhi[so] = *(const uint4*)(Ahi + ga);
            *(uint4*)&sAlo[so] = *(const uint4*)(Alo + ga);
            *(uint4*)&sBhi[so] = *(const uint4*)(bhi + gb);
            *(uint4*)&sBlo[so] = *(const uint4*)(blo + gb);
        }
        __syncthreads();

#pragma unroll
        for (int kk = 0; kk < 2; kk++) {
            int k16 = kk * 16;
            uint32_t ahi[2][4], alo[2][4];
#pragma unroll
            for (int mt = 0; mt < 2; mt++) {
                uint32_t off = 2u * ((wm * 32 + mt * 16 + a_row) * PITCH + k16 + a_col);
                LDSM4(ahi[mt][0], ahi[mt][1], ahi[mt][2], ahi[mt][3], uAhi + off);
                LDSM4(alo[mt][0], alo[mt][1], alo[mt][2], alo[mt][3], uAlo + off);
            }
#pragma unroll
            for (int np = 0; np < 4; np++) {
                uint32_t off = 2u * ((wn * 64 + np * 16 + b_row) * PITCH + k16 + b_col);
                uint32_t bh0, bh1, bh2, bh3, bl0, bl1, bl2, bl3;
                LDSM4(bh0, bh1, bh2, bh3, uBhi + off);
                LDSM4(bl0, bl1, bl2, bl3, uBlo + off);
#pragma unroll
                for (int mt = 0; mt < 2; mt++) {
                    MMA16816(acc[mt][np * 2 + 0], ahi[mt], bh0, bh1);
                    MMA16816(acc[mt][np * 2 + 0], ahi[mt], bl0, bl1);
                    MMA16816(acc[mt][np * 2 + 0], alo[mt], bh0, bh1);
                    MMA16816(acc[mt][np * 2 + 1], ahi[mt], bh2, bh3);
                    MMA16816(acc[mt][np * 2 + 1], ahi[mt], bl2, bl3);
                    MMA16816(acc[mt][np * 2 + 1], alo[mt], bh2, bh3);
                }
            }
        }
    }

#pragma unroll
    for (int mt = 0; mt < 2; mt++) {
#pragma unroll
        for (int nt = 0; nt < 8; nt++) {
            int row = m0 + wm * 32 + mt * 16 + (lane >> 2);
            int col = n0 + wn * 64 + nt * 8 + (lane & 3) * 2;
            float b0 = bp[col], b1 = bp[col + 1];
            float2 v0 = make_float2(acc[mt][nt][0] + b0, acc[mt][nt][1] + b1);
            float2 v1 = make_float2(acc[mt][nt][2] + b0, acc[mt][nt][3] + b1);
            *(float2*)&C[(size_t)row * Gc + col]       = v0;
            *(float2*)&C[(size_t)(row + 8) * Gc + col] = v1;
        }
    }
}

// ---------------- grid barrier ----------------
__device__ __forceinline__ void grid_barrier(int* lgen) {
    __syncthreads();
    if (threadIdx.x == 0) {
        int g = *lgen;
        if (atomicAdd(&g_bar_count, 1) == NBLK - 1) {
            g_bar_count = 0;
            __threadfence();
            g_bar_gen = g + 1;
        } else {
            while (g_bar_gen == g) { }
        }
        *lgen = g + 1;
    }
    __syncthreads();
}

// ---------------- persistent MMA recurrence ----------------
// Grid (64,1,2), 128 threads (4 warps). Block owns hidden units [j0,j0+8)
// -> 24 gate rows (padded to 32), all 64 batch. Per step: gh = h @ Wslice^T
// via m16n8k16 bf16 3-product split; gate math block-local.
// smem: Whi/Wlo [32][520], Hhi/Hlo [64][520], G [24][72] floats.
#define RPITCH 520
#define OFF_WHI 0
#define OFF_WLO 33280
#define OFF_HHI 66560
#define OFF_HLO 133120
#define OFF_G   199680
#define PERSIST_SMEM 206592

__global__ void __launch_bounds__(128, 1)
gru_persist_mma(const float* __restrict__ w_hh,
                const float* __restrict__ b_hh,
                float* __restrict__ out_l1,
                int layer)
{
    extern __shared__ char sm[];
    __nv_bfloat16* sWhi = (__nv_bfloat16*)(sm + OFF_WHI);
    __nv_bfloat16* sWlo = (__nv_bfloat16*)(sm + OFF_WLO);
    __nv_bfloat16* sHhi = (__nv_bfloat16*)(sm + OFF_HHI);
    __nv_bfloat16* sHlo = (__nv_bfloat16*)(sm + OFF_HLO);
    float* sG = (float*)(sm + OFF_G);    // [24][72]

    int tid = threadIdx.x, lane = tid & 31, wid = tid >> 5;
    int dir = blockIdx.z;
    int j0  = blockIdx.x * 8;
    int jl  = tid >> 4;      // 0..7  (gate phase)
    int bg  = tid & 15;      // 0..15
    int jglob = j0 + jl;

    // one-time: load + split W slice into smem (rows 24..31 zero pad)
    const float* W = w_hh + (size_t)dir * Gc * Hc;
    for (int idx = tid; idx < 32 * 512; idx += 128) {
        int r = idx >> 9, k = idx & 511;
        float w = 0.0f;
        if (r < 24) {
            int gg = r >> 3, jj = r & 7;
            w = W[(size_t)(gg * Hc + j0 + jj) * Hc + k];
        }
        __nv_bfloat16 h = __float2bfloat16(w);
        sWhi[r * RPITCH + k] = h;
        sWlo[r * RPITCH + k] = __float2bfloat16(w - __bfloat162float(h));
    }
    float br = __ldg(&b_hh[dir * Gc + jglob]);
    float bz = __ldg(&b_hh[dir * Gc + Hc + jglob]);
    float bn = __ldg(&b_hh[dir * Gc + 2 * Hc + jglob]);

    const float* gx = g_gx + (size_t)dir * M_TOK * Gc;
    float* hs = (layer == 0) ? g_h0out : out_l1;

    uint32_t uWhi = smem_u32(sWhi), uWlo = smem_u32(sWlo);
    uint32_t uHhi = smem_u32(sHhi), uHlo = smem_u32(sHlo);

    int a_row = lane & 15, a_col = (lane >> 4) * 8;
    int b_row = (lane & 7) + ((lane >> 4) & 1) * 8, b_col = ((lane >> 3) & 1) * 8;
    int m_base = wid * 16;

    int lgen = g_bar_gen;
    __syncthreads();

    for (int s = 0; s < Tc; s++) {
        int rbuf = s & 1;
        int t = dir ? (Tc - 1 - s) : s;
        const __nv_bfloat16* hAhi = g_hAhi[rbuf] + dir * Bc * Hc;
        const __nv_bfloat16* hAlo = g_hAlo[rbuf] + dir * Bc * Hc;
        __nv_bfloat16* wAhi = g_hAhi[rbuf ^ 1] + dir * Bc * Hc;
        __nv_bfloat16* wAlo = g_hAlo[rbuf ^ 1] + dir * Bc * Hc;

        // prefetch gx for this thread's 12 gate values (DRAM latency hides
        // behind staging + mma)
        float pgr[4], pgz[4], pgn[4];
#pragma unroll
        for (int q = 0; q < 4; q++) {
            int b = bg * 4 + q;
            size_t gb = ((size_t)b * Tc + t) * Gc;
            pgr[q] = __ldg(&gx[gb + jglob]);
            pgz[q] = __ldg(&gx[gb + Hc + jglob]);
            pgn[q] = __ldg(&gx[gb + 2 * Hc + jglob]);
        }

        // stage h (both splits) into smem; .cg (L2) — written by other SMs
#pragma unroll 8
        for (int p = 0; p < 32; p++) {
            int idx = tid + p * 128;        // 0..4095
            int rrow = idx >> 6, c8 = idx & 63;
            uint4 vh = __ldcg((const uint4*)(hAhi + rrow * Hc + c8 * 8));
            uint4 vl = __ldcg((const uint4*)(hAlo + rrow * Hc + c8 * 8));
            *(uint4*)&sHhi[rrow * RPITCH + c8 * 8] = vh;
            *(uint4*)&sHlo[rrow * RPITCH + c8 * 8] = vl;
        }
        __syncthreads();

        // gh = h @ Wslice^T   (M=64, N=32, K=512)
        float acc[4][4];
#pragma unroll
        for (int i = 0; i < 4; i++)
#pragma unroll
            for (int q = 0; q < 4; q++) acc[i][q] = 0.0f;

#pragma unroll 4
        for (int k16 = 0; k16 < 32; k16++) {
            uint32_t offA = (uint32_t)(((m_base + a_row) * RPITCH + k16 * 16 + a_col) * 2);
            uint32_t ahi[4], alo[4];
            LDSM4(ahi[0], ahi[1], ahi[2], ahi[3], uHhi + offA);
            LDSM4(alo[0], alo[1], alo[2], alo[3], uHlo + offA);
#pragma unroll
            for (int nb = 0; nb < 2; nb++) {
                uint32_t offB = (uint32_t)(((nb * 16 + b_row) * RPITCH + k16 * 16 + b_col) * 2);
                uint32_t bh0, bh1, bh2, bh3, bl0, bl1, bl2, bl3;
                LDSM4(bh0, bh1, bh2, bh3, uWhi + offB);
                LDSM4(bl0, bl1, bl2, bl3, uWlo + offB);
                MMA16816(acc[nb * 2 + 0], ahi, bh0, bh1);
                MMA16816(acc[nb * 2 + 0], ahi, bl0, bl1);
                MMA16816(acc[nb * 2 + 0], alo, bh0, bh1);
                MMA16816(acc[nb * 2 + 1], ahi, bh2, bh3);
                MMA16816(acc[nb * 2 + 1], ahi, bl2, bl3);
                MMA16816(acc[nb * 2 + 1], alo, bh2, bh3);
            }
        }

        // dump gh (cols 0..23) to sG[col][row]
#pragma unroll
        for (int nt = 0; nt < 3; nt++) {
            int c0 = nt * 8 + (lane & 3) * 2;
            int r0 = m_base + (lane >> 2);
            sG[c0 * 72 + r0]           = acc[nt][0];
            sG[(c0 + 1) * 72 + r0]     = acc[nt][1];
            sG[c0 * 72 + r0 + 8]       = acc[nt][2];
            sG[(c0 + 1) * 72 + r0 + 8] = acc[nt][3];
        }
        __syncthreads();

        // gate math: thread (jl,bg) -> unit jglob, batches 4bg..4bg+3
#pragma unroll
        for (int q = 0; q < 4; q++) {
            int b = bg * 4 + q;
            float ghr = sG[jl * 72 + b];
            float ghz = sG[(8 + jl) * 72 + b];
            float ghn = sG[(16 + jl) * 72 + b];
            float hp = __bfloat162float(sHhi[b * RPITCH + jglob])
                     + __bfloat162float(sHlo[b * RPITCH + jglob]);
            float rr = 1.0f / (1.0f + expf(-(pgr[q] + ghr + br)));
            float zz = 1.0f / (1.0f + expf(-(pgz[q] + ghz + bz)));
            float nn = tanhf(pgn[q] + rr * (ghn + bn));
            float hv = (1.0f - zz) * nn + zz * hp;
            hs[((size_t)b * Tc + t) * (2 * Hc) + dir * Hc + jglob] = hv;
            __nv_bfloat16 hh = __float2bfloat16(hv);
            wAhi[b * Hc + jglob] = hh;
            wAlo[b * Hc + jglob] = __float2bfloat16(hv - __bfloat162float(hh));
        }

        __threadfence();
        if (s != Tc - 1) grid_barrier(&lgen);
    }
}

// ---------------- copy final hidden states ----------------
__global__ void hy_copy_kernel(float* __restrict__ d_out, int layer) {
    int i = blockIdx.x * blockDim.x + threadIdx.x;   // 0..65535
    int dir = i >> 15;
    int rem = i & 32767;                              // = b*512 + j
    d_out[HY_OFF + (size_t)(2 * layer + dir) * Bc * Hc + rem] =
        __bfloat162float(g_hAhi[0][dir * Bc * Hc + rem]) +
        __bfloat162float(g_hAlo[0][dir * Bc * Hc + rem]);
}

// ---------------- launch ----------------
extern "C" void kernel_launch(void* const* d_in, const int* in_sizes, int n_in,
                              void* d_out, int out_size)
{
    const float* xs    = (const float*)d_in[0];
    const float* w_ih0 = (const float*)d_in[1];
    const float* w_hh0 = (const float*)d_in[2];
    const float* b_ih0 = (const float*)d_in[3];
    const float* b_hh0 = (const float*)d_in[4];
    const float* w_ih1 = (const float*)d_in[5];
    const float* w_hh1 = (const float*)d_in[6];
    const float* b_ih1 = (const float*)d_in[7];
    const float* b_hh1 = (const float*)d_in[8];
    float* out = (float*)d_out;

    cudaFuncSetAttribute(gru_persist_mma,
                         cudaFuncAttributeMaxDynamicSharedMemorySize, PERSIST_SMEM);

    __nv_bfloat16 *xs_hi, *xs_lo, *h0_hi, *h0_lo, *w0_hi, *w0_lo, *w1_hi, *w1_lo;
    cudaGetSymbolAddress((void**)&xs_hi, g_xs_hi);
    cudaGetSymbolAddress((void**)&xs_lo, g_xs_lo);
    cudaGetSymbolAddress((void**)&h0_hi, g_h0_hi);
    cudaGetSymbolAddress((void**)&h0_lo, g_h0_lo);
    cudaGetSymbolAddress((void**)&w0_hi, g_w0_hi);
    cudaGetSymbolAddress((void**)&w0_lo, g_w0_lo);
    cudaGetSymbolAddress((void**)&w1_hi, g_w1_hi);
    cudaGetSymbolAddress((void**)&w1_lo, g_w1_lo);
    float* h0out;
    cudaGetSymbolAddress((void**)&h0out, g_h0out);

    dim3 gemm_grid(Gc / 128, M_TOK / 128, 2);   // (12, 256, 2)
    dim3 persist_grid(Hc / 8, 1, 2);            // 128 blocks

    size_t n_w0 = (size_t)2 * Gc * Ec;
    size_t n_w1 = (size_t)2 * Gc * 2 * Hc;
    size_t n_xs = (size_t)M_TOK * Ec;
    size_t n_h0 = (size_t)M_TOK * 2 * Hc;

    split_bf16_kernel<<<(unsigned)((n_w0 + 255) / 256), 256>>>(w_ih0, w0_hi, w0_lo, n_w0);
    split_bf16_kernel<<<(unsigned)((n_w1 + 255) / 256), 256>>>(w_ih1, w1_hi, w1_lo, n_w1);
    split_bf16_kernel<<<(unsigned)((n_xs + 255) / 256), 256>>>(xs, xs_hi, xs_lo, n_xs);

    // ---- layer 0 ----
    gemm_mma<<<gemm_grid, 256>>>(xs_hi, xs_lo, w0_hi, w0_lo, b_ih0, Ec);
    zero_h_kernel<<<(2 * Bc * Hc) / 256, 256>>>();
    gru_persist_mma<<<persist_grid, 128, PERSIST_SMEM>>>(w_hh0, b_hh0, out, 0);
    hy_copy_kernel<<<(2 * Bc * Hc) / 256, 256>>>(out, 0);

    // ---- layer 1 ----
    split_bf16_kernel<<<(unsigned)((n_h0 + 255) / 256), 256>>>(h0out, h0_hi, h0_lo, n_h0);
    gemm_mma<<<gemm_grid, 256>>>(h0_hi, h0_lo, w1_hi, w1_lo, b_ih1, 2 * Hc);
    zero_h_kernel<<<(2 * Bc * Hc) / 256, 256>>>();
    gru_persist_mma<<<persist_grid, 128, PERSIST_SMEM>>>(w_hh1, b_hh1, out, 1);
    hy_copy_kernel<<<(2 * Bc * Hc) / 256, 256>>>(out, 1);
}

// round 6
// speedup vs baseline: 2.2846x; 1.0402x over previous
#include <cuda_runtime.h>
#include <cuda_bf16.h>
#include <cstdint>
#include <math.h>

#define Bc 64
#define Tc 512
#define Ec 512
#define Hc 512
#define Gc 1536            // 3*H
#define M_TOK (Bc*Tc)      // 32768 tokens
#define HY_OFF ((size_t)Bc*Tc*2*Hc)
#define NBLK_DIR 64        // blocks per direction

// ---------------- device scratch ----------------
__device__ float g_gx[(size_t)2*M_TOK*Gc];       // [dir][b*T+t][3H]
__device__ float g_h0out[(size_t)M_TOK*2*Hc];    // layer0 output [b][t][2H]

// h state as bf16 hi/lo split, layout [buf][dir][batch b][hidden j]
__device__ __nv_bfloat16 g_hAhi[2][2*Bc*Hc];
__device__ __nv_bfloat16 g_hAlo[2][2*Bc*Hc];

// bf16 split operands for gx GEMMs
__device__ __nv_bfloat16 g_xs_hi[(size_t)M_TOK*Ec],  g_xs_lo[(size_t)M_TOK*Ec];
__device__ __nv_bfloat16 g_h0_hi[(size_t)M_TOK*2*Hc], g_h0_lo[(size_t)M_TOK*2*Hc];
__device__ __nv_bfloat16 g_w0_hi[(size_t)2*Gc*Ec],   g_w0_lo[(size_t)2*Gc*Ec];
__device__ __nv_bfloat16 g_w1_hi[(size_t)2*Gc*2*Hc], g_w1_lo[(size_t)2*Gc*2*Hc];

// per-direction barrier state (padded to separate cache lines)
__device__ int g_bar_cnt[2 * 32];
__device__ volatile int g_bar_gen2[2 * 32];

// warp-mma helpers (base PTX, no 'a'-features)
#define LDSM4(r0, r1, r2, r3, addr) \
    asm volatile("ldmatrix.sync.aligned.m8n8.x4.shared.b16 {%0,%1,%2,%3}, [%4];" \
                 : "=r"(r0), "=r"(r1), "=r"(r2), "=r"(r3) : "r"(addr))

#define LDSM2(r0, r1, addr) \
    asm volatile("ldmatrix.sync.aligned.m8n8.x2.shared.b16 {%0,%1}, [%2];" \
                 : "=r"(r0), "=r"(r1) : "r"(addr))

#define MMA16816(d, a, b0, b1) \
    asm volatile("mma.sync.aligned.m16n8k16.row.col.f32.bf16.bf16.f32 " \
                 "{%0,%1,%2,%3}, {%4,%5,%6,%7}, {%8,%9}, {%0,%1,%2,%3};" \
                 : "+f"(d[0]), "+f"(d[1]), "+f"(d[2]), "+f"(d[3]) \
                 : "r"(a[0]), "r"(a[1]), "r"(a[2]), "r"(a[3]), "r"(b0), "r"(b1))

__device__ __forceinline__ uint32_t smem_u32(const void* p) {
    uint32_t a;
    asm("{ .reg .u64 t; cvta.to.shared.u64 t, %1; cvt.u32.u64 %0, t; }" : "=r"(a) : "l"(p));
    return a;
}

// ---------------- bf16 split prep ----------------
__global__ void split_bf16_kernel(const float* __restrict__ src,
                                  __nv_bfloat16* __restrict__ hi,
                                  __nv_bfloat16* __restrict__ lo, size_t n) {
    size_t i = (size_t)blockIdx.x * blockDim.x + threadIdx.x;
    if (i >= n) return;
    float a = src[i];
    __nv_bfloat16 h = __float2bfloat16(a);
    hi[i] = h;
    lo[i] = __float2bfloat16(a - __bfloat162float(h));
}

// ---------------- zero hidden state (buf 0, both splits) ----------------
__global__ void zero_h_kernel() {
    int i = blockIdx.x * blockDim.x + threadIdx.x;   // 2*B*H = 65536
    g_hAhi[0][i] = __float2bfloat16(0.0f);
    g_hAlo[0][i] = __float2bfloat16(0.0f);
}

// ---------------- tensor-core gx GEMM (unchanged from passing R4/R5) -------
#define KC 32
#define PITCH 40

__global__ void __launch_bounds__(256, 2)
gemm_mma(const __nv_bfloat16* __restrict__ Ahi, const __nv_bfloat16* __restrict__ Alo,
         const __nv_bfloat16* __restrict__ Whi, const __nv_bfloat16* __restrict__ Wlo,
         const float* __restrict__ bias, int K)
{
    __shared__ __nv_bfloat16 sAhi[128 * PITCH], sAlo[128 * PITCH];
    __shared__ __nv_bfloat16 sBhi[128 * PITCH], sBlo[128 * PITCH];

    int tid  = threadIdx.x;
    int wid  = tid >> 5, lane = tid & 31;
    int dir  = blockIdx.z;
    int n0   = blockIdx.x * 128;
    int m0   = blockIdx.y * 128;
    int wm   = wid >> 1;
    int wn   = wid & 1;

    const __nv_bfloat16* bhi = Whi + (size_t)dir * Gc * K;
    const __nv_bfloat16* blo = Wlo + (size_t)dir * Gc * K;
    float* C = g_gx + (size_t)dir * M_TOK * Gc;
    const float* bp = bias + dir * Gc;

    float acc[2][8][4];
#pragma unroll
    for (int i = 0; i < 2; i++)
#pragma unroll
        for (int j = 0; j < 8; j++)
#pragma unroll
            for (int q = 0; q < 4; q++) acc[i][j][q] = 0.0f;

    uint32_t uAhi = smem_u32(sAhi), uAlo = smem_u32(sAlo);
    uint32_t uBhi = smem_u32(sBhi), uBlo = smem_u32(sBlo);

    int a_row = (lane & 15);
    int a_col = (lane >> 4) * 8;
    int b_row = (lane & 7) + ((lane >> 4) & 1) * 8;
    int b_col = ((lane >> 3) & 1) * 8;

    const int nchunks = K / KC;
    for (int c = 0; c < nchunks; c++) {
        int k0 = c * KC;
        __syncthreads();
#pragma unroll
        for (int p = 0; p < 2; p++) {
            int idx = p * 256 + tid;
            int r   = idx >> 2;
            int c4  = idx & 3;
            size_t ga = (size_t)(m0 + r) * K + k0 + c4 * 8;
            size_t gb = (size_t)(n0 + r) * K + k0 + c4 * 8;
            int so = r * PITCH + c4 * 8;
            *(uint4*)&sAhi[so] = *(const uint4*)(Ahi + ga);
            *(uint4*)&sAlo[so] = *(const uint4*)(Alo + ga);
            *(uint4*)&sBhi[so] = *(const uint4*)(bhi + gb);
            *(uint4*)&sBlo[so] = *(const uint4*)(blo + gb);
        }
        __syncthreads();

#pragma unroll
        for (int kk = 0; kk < 2; kk++) {
            int k16 = kk * 16;
            uint32_t ahi[2][4], alo[2][4];
#pragma unroll
            for (int mt = 0; mt < 2; mt++) {
                uint32_t off = 2u * ((wm * 32 + mt * 16 + a_row) * PITCH + k16 + a_col);
                LDSM4(ahi[mt][0], ahi[mt][1], ahi[mt][2], ahi[mt][3], uAhi + off);
                LDSM4(alo[mt][0], alo[mt][1], alo[mt][2], alo[mt][3], uAlo + off);
            }
#pragma unroll
            for (int np = 0; np < 4; np++) {
                uint32_t off = 2u * ((wn * 64 + np * 16 + b_row) * PITCH + k16 + b_col);
                uint32_t bh0, bh1, bh2, bh3, bl0, bl1, bl2, bl3;
                LDSM4(bh0, bh1, bh2, bh3, uBhi + off);
                LDSM4(bl0, bl1, bl2, bl3, uBlo + off);
#pragma unroll
                for (int mt = 0; mt < 2; mt++) {
                    MMA16816(acc[mt][np * 2 + 0], ahi[mt], bh0, bh1);
                    MMA16816(acc[mt][np * 2 + 0], ahi[mt], bl0, bl1);
                    MMA16816(acc[mt][np * 2 + 0], alo[mt], bh0, bh1);
                    MMA16816(acc[mt][np * 2 + 1], ahi[mt], bh2, bh3);
                    MMA16816(acc[mt][np * 2 + 1], ahi[mt], bl2, bl3);
                    MMA16816(acc[mt][np * 2 + 1], alo[mt], bh2, bh3);
                }
            }
        }
    }

#pragma unroll
    for (int mt = 0; mt < 2; mt++) {
#pragma unroll
        for (int nt = 0; nt < 8; nt++) {
            int row = m0 + wm * 32 + mt * 16 + (lane >> 2);
            int col = n0 + wn * 64 + nt * 8 + (lane & 3) * 2;
            float b0 = bp[col], b1 = bp[col + 1];
            float2 v0 = make_float2(acc[mt][nt][0] + b0, acc[mt][nt][1] + b1);
            float2 v1 = make_float2(acc[mt][nt][2] + b0, acc[mt][nt][3] + b1);
            *(float2*)&C[(size_t)row * Gc + col]       = v0;
            *(float2*)&C[(size_t)(row + 8) * Gc + col] = v1;
        }
    }
}

// ---------------- persistent MMA recurrence ----------------
// Grid (64,1,2), 128 threads. Block owns units [j0,j0+8) (24 gate rows), all
// 64 batch. Per-dir barrier; h_new/hs exchanged via smem for coalesced writes.
#define RPITCH 520
#define OFF_WHI 0
#define OFF_WLO 33280
#define OFF_HHI 66560
#define OFF_HLO 133120
#define OFF_G   199680                       // [24][72] floats
#define OFF_X   (OFF_G + 24*72*4)            // [64][8]  floats
#define PERSIST_SMEM (OFF_X + 64*8*4)

__global__ void __launch_bounds__(128, 1)
gru_persist_mma(const float* __restrict__ w_hh,
                const float* __restrict__ b_hh,
                float* __restrict__ out_l1,
                int layer)
{
    extern __shared__ char sm[];
    __nv_bfloat16* sWhi = (__nv_bfloat16*)(sm + OFF_WHI);
    __nv_bfloat16* sWlo = (__nv_bfloat16*)(sm + OFF_WLO);
    __nv_bfloat16* sHhi = (__nv_bfloat16*)(sm + OFF_HHI);
    __nv_bfloat16* sHlo = (__nv_bfloat16*)(sm + OFF_HLO);
    float* sG = (float*)(sm + OFF_G);    // [24][72]
    float* sX = (float*)(sm + OFF_X);    // [64][8]  h_new exchange

    int tid = threadIdx.x, lane = tid & 31, wid = tid >> 5;
    int dir = blockIdx.z;
    int j0  = blockIdx.x * 8;
    int jl  = tid >> 4;      // 0..7
    int bg  = tid & 15;      // 0..15
    int jglob = j0 + jl;

    // one-time: load + split W slice into smem (rows 24..31 zero pad)
    const float* W = w_hh + (size_t)dir * Gc * Hc;
    for (int idx = tid; idx < 32 * 512; idx += 128) {
        int r = idx >> 9, k = idx & 511;
        float w = 0.0f;
        if (r < 24) {
            int gg = r >> 3, jj = r & 7;
            w = W[(size_t)(gg * Hc + j0 + jj) * Hc + k];
        }
        __nv_bfloat16 h = __float2bfloat16(w);
        sWhi[r * RPITCH + k] = h;
        sWlo[r * RPITCH + k] = __float2bfloat16(w - __bfloat162float(h));
    }
    float br = __ldg(&b_hh[dir * Gc + jglob]);
    float bz = __ldg(&b_hh[dir * Gc + Hc + jglob]);
    float bn = __ldg(&b_hh[dir * Gc + 2 * Hc + jglob]);

    const float* gx = g_gx + (size_t)dir * M_TOK * Gc;
    float* hs = (layer == 0) ? g_h0out : out_l1;

    uint32_t uWhi = smem_u32(sWhi), uWlo = smem_u32(sWlo);
    uint32_t uHhi = smem_u32(sHhi), uHlo = smem_u32(sHlo);

    int a_row = lane & 15, a_col = (lane >> 4) * 8;
    int b_row = (lane & 7) + ((lane >> 4) & 1) * 8, b_col = ((lane >> 3) & 1) * 8;
    int b_row2 = 16 + (lane & 7);    // nb1 (x2) rows
    int m_base = wid * 16;

    // writer thread mapping for coalesced global writes
    int wb = tid >> 1;               // batch 0..63
    int wj = (tid & 1) * 4;          // j-quad 0 or 4

    int lgen = g_bar_gen2[dir * 32];
    __syncthreads();

    // prefetch gx for s = 0
    float pgr[4], pgz[4], pgn[4];
    {
        int t0 = dir ? (Tc - 1) : 0;
#pragma unroll
        for (int q = 0; q < 4; q++) {
            int b = bg * 4 + q;
            size_t gb = ((size_t)b * Tc + t0) * Gc;
            pgr[q] = __ldg(&gx[gb + jglob]);
            pgz[q] = __ldg(&gx[gb + Hc + jglob]);
            pgn[q] = __ldg(&gx[gb + 2 * Hc + jglob]);
        }
    }

    for (int s = 0; s < Tc; s++) {
        int rbuf = s & 1;
        int t = dir ? (Tc - 1 - s) : s;
        const __nv_bfloat16* hAhi = g_hAhi[rbuf] + dir * Bc * Hc;
        const __nv_bfloat16* hAlo = g_hAlo[rbuf] + dir * Bc * Hc;
        __nv_bfloat16* wAhi = g_hAhi[rbuf ^ 1] + dir * Bc * Hc;
        __nv_bfloat16* wAlo = g_hAlo[rbuf ^ 1] + dir * Bc * Hc;

        // stage h (both splits) into smem
#pragma unroll 8
        for (int p = 0; p < 32; p++) {
            int idx = tid + p * 128;        // 0..4095
            int rrow = idx >> 6, c8 = idx & 63;
            uint4 vh = __ldcg((const uint4*)(hAhi + rrow * Hc + c8 * 8));
            uint4 vl = __ldcg((const uint4*)(hAlo + rrow * Hc + c8 * 8));
            *(uint4*)&sHhi[rrow * RPITCH + c8 * 8] = vh;
            *(uint4*)&sHlo[rrow * RPITCH + c8 * 8] = vl;
        }
        __syncthreads();

        // gh = h @ Wslice^T   (M=64, N=24, K=512), 3-product bf16 split
        float acc[3][4];
#pragma unroll
        for (int i = 0; i < 3; i++)
#pragma unroll
            for (int q = 0; q < 4; q++) acc[i][q] = 0.0f;

#pragma unroll 4
        for (int k16 = 0; k16 < 32; k16++) {
            uint32_t offA = (uint32_t)(((m_base + a_row) * RPITCH + k16 * 16 + a_col) * 2);
            uint32_t ahi[4], alo[4];
            LDSM4(ahi[0], ahi[1], ahi[2], ahi[3], uHhi + offA);
            LDSM4(alo[0], alo[1], alo[2], alo[3], uHlo + offA);

            // nb0: gate rows 0..15
            uint32_t offB = (uint32_t)((b_row * RPITCH + k16 * 16 + b_col) * 2);
            uint32_t bh0, bh1, bh2, bh3, bl0, bl1, bl2, bl3;
            LDSM4(bh0, bh1, bh2, bh3, uWhi + offB);
            LDSM4(bl0, bl1, bl2, bl3, uWlo + offB);
            MMA16816(acc[0], ahi, bh0, bh1);
            MMA16816(acc[0], ahi, bl0, bl1);
            MMA16816(acc[0], alo, bh0, bh1);
            MMA16816(acc[1], ahi, bh2, bh3);
            MMA16816(acc[1], ahi, bl2, bl3);
            MMA16816(acc[1], alo, bh2, bh3);

            // nb1: gate rows 16..23 (x2 ldsm)
            uint32_t offB2 = (uint32_t)((b_row2 * RPITCH + k16 * 16 + b_col) * 2);
            uint32_t ch0, ch1, cl0, cl1;
            LDSM2(ch0, ch1, uWhi + offB2);
            LDSM2(cl0, cl1, uWlo + offB2);
            MMA16816(acc[2], ahi, ch0, ch1);
            MMA16816(acc[2], ahi, cl0, cl1);
            MMA16816(acc[2], alo, ch0, ch1);
        }

        // dump gh (cols 0..23) to sG[col][row]
#pragma unroll
        for (int nt = 0; nt < 3; nt++) {
            int c0 = nt * 8 + (lane & 3) * 2;
            int r0 = m_base + (lane >> 2);
            sG[c0 * 72 + r0]           = acc[nt][0];
            sG[(c0 + 1) * 72 + r0]     = acc[nt][1];
            sG[c0 * 72 + r0 + 8]       = acc[nt][2];
            sG[(c0 + 1) * 72 + r0 + 8] = acc[nt][3];
        }
        __syncthreads();

        // gate math: thread (jl,bg) -> unit jglob, batches 4bg..4bg+3
#pragma unroll
        for (int q = 0; q < 4; q++) {
            int b = bg * 4 + q;
            float ghr = sG[jl * 72 + b];
            float ghz = sG[(8 + jl) * 72 + b];
            float ghn = sG[(16 + jl) * 72 + b];
            float hp = __bfloat162float(sHhi[b * RPITCH + jglob])
                     + __bfloat162float(sHlo[b * RPITCH + jglob]);
            float rr = 1.0f / (1.0f + __expf(-(pgr[q] + ghr + br)));
            float zz = 1.0f / (1.0f + __expf(-(pgz[q] + ghz + bz)));
            float nn = tanhf(pgn[q] + rr * (ghn + bn));
            float hv = (1.0f - zz) * nn + zz * hp;
            sX[b * 8 + jl] = hv;
        }
        __syncthreads();

        // coalesced h_new global write: thread -> (batch wb, j-quad wj)
        {
            float v0 = sX[wb * 8 + wj + 0];
            float v1 = sX[wb * 8 + wj + 1];
            float v2 = sX[wb * 8 + wj + 2];
            float v3 = sX[wb * 8 + wj + 3];
            __nv_bfloat16 h0 = __float2bfloat16(v0), h1 = __float2bfloat16(v1);
            __nv_bfloat16 h2 = __float2bfloat16(v2), h3 = __float2bfloat16(v3);
            __nv_bfloat162 hi01 = {h0, h1}, hi23 = {h2, h3};
            __nv_bfloat162 lo01 = {__float2bfloat16(v0 - __bfloat162float(h0)),
                                   __float2bfloat16(v1 - __bfloat162float(h1))};
            __nv_bfloat162 lo23 = {__float2bfloat16(v2 - __bfloat162float(h2)),
                                   __float2bfloat16(v3 - __bfloat162float(h3))};
            *(__nv_bfloat162*)(wAhi + wb * Hc + j0 + wj)     = hi01;
            *(__nv_bfloat162*)(wAhi + wb * Hc + j0 + wj + 2) = hi23;
            *(__nv_bfloat162*)(wAlo + wb * Hc + j0 + wj)     = lo01;
            *(__nv_bfloat162*)(wAlo + wb * Hc + j0 + wj + 2) = lo23;
        }
        __threadfence();
        __syncthreads();

        // barrier arrive (skip on last step; keeps counters zeroed at exit)
        int was_last = 0;
        if (s != Tc - 1 && tid == 0) {
            was_last = (atomicAdd(&g_bar_cnt[dir * 32], 1) == NBLK_DIR - 1);
        }

        // off-critical-path work while others arrive:
        // 1) hs output (coalesced float4 via sX)
        {
            float4 xv = make_float4(sX[wb * 8 + wj], sX[wb * 8 + wj + 1],
                                    sX[wb * 8 + wj + 2], sX[wb * 8 + wj + 3]);
            *(float4*)&hs[((size_t)wb * Tc + t) * (2 * Hc) + dir * Hc + j0 + wj] = xv;
        }
        // 2) prefetch gx for next step (clamped)
        {
            int sn = (s + 1 < Tc) ? s + 1 : s;
            int tn = dir ? (Tc - 1 - sn) : sn;
#pragma unroll
            for (int q = 0; q < 4; q++) {
                int b = bg * 4 + q;
                size_t gb = ((size_t)b * Tc + tn) * Gc;
                pgr[q] = __ldg(&gx[gb + jglob]);
                pgz[q] = __ldg(&gx[gb + Hc + jglob]);
                pgn[q] = __ldg(&gx[gb + 2 * Hc + jglob]);
            }
        }

        if (s != Tc - 1) {
            if (tid == 0) {
                if (was_last) {
                    g_bar_cnt[dir * 32] = 0;
                    __threadfence();
                    g_bar_gen2[dir * 32] = lgen + 1;
                } else {
                    while (g_bar_gen2[dir * 32] == lgen) { }
                }
                lgen = lgen + 1;
            }
            __syncthreads();
        }
    }
}

// ---------------- copy final hidden states ----------------
__global__ void hy_copy_kernel(float* __restrict__ d_out, int layer) {
    int i = blockIdx.x * blockDim.x + threadIdx.x;   // 0..65535
    int dir = i >> 15;
    int rem = i & 32767;                              // = b*512 + j
    d_out[HY_OFF + (size_t)(2 * layer + dir) * Bc * Hc + rem] =
        __bfloat162float(g_hAhi[0][dir * Bc * Hc + rem]) +
        __bfloat162float(g_hAlo[0][dir * Bc * Hc + rem]);
}

// ---------------- launch ----------------
extern "C" void kernel_launch(void* const* d_in, const int* in_sizes, int n_in,
                              void* d_out, int out_size)
{
    const float* xs    = (const float*)d_in[0];
    const float* w_ih0 = (const float*)d_in[1];
    const float* w_hh0 = (const float*)d_in[2];
    const float* b_ih0 = (const float*)d_in[3];
    const float* b_hh0 = (const float*)d_in[4];
    const float* w_ih1 = (const float*)d_in[5];
    const float* w_hh1 = (const float*)d_in[6];
    const float* b_ih1 = (const float*)d_in[7];
    const float* b_hh1 = (const float*)d_in[8];
    float* out = (float*)d_out;

    cudaFuncSetAttribute(gru_persist_mma,
                         cudaFuncAttributeMaxDynamicSharedMemorySize, PERSIST_SMEM);

    __nv_bfloat16 *xs_hi, *xs_lo, *h0_hi, *h0_lo, *w0_hi, *w0_lo, *w1_hi, *w1_lo;
    cudaGetSymbolAddress((void**)&xs_hi, g_xs_hi);
    cudaGetSymbolAddress((void**)&xs_lo, g_xs_lo);
    cudaGetSymbolAddress((void**)&h0_hi, g_h0_hi);
    cudaGetSymbolAddress((void**)&h0_lo, g_h0_lo);
    cudaGetSymbolAddress((void**)&w0_hi, g_w0_hi);
    cudaGetSymbolAddress((void**)&w0_lo, g_w0_lo);
    cudaGetSymbolAddress((void**)&w1_hi, g_w1_hi);
    cudaGetSymbolAddress((void**)&w1_lo, g_w1_lo);
    float* h0out;
    cudaGetSymbolAddress((void**)&h0out, g_h0out);

    dim3 gemm_grid(Gc / 128, M_TOK / 128, 2);   // (12, 256, 2)
    dim3 persist_grid(Hc / 8, 1, 2);            // 128 blocks

    size_t n_w0 = (size_t)2 * Gc * Ec;
    size_t n_w1 = (size_t)2 * Gc * 2 * Hc;
    size_t n_xs = (size_t)M_TOK * Ec;
    size_t n_h0 = (size_t)M_TOK * 2 * Hc;

    split_bf16_kernel<<<(unsigned)((n_w0 + 255) / 256), 256>>>(w_ih0, w0_hi, w0_lo, n_w0);
    split_bf16_kernel<<<(unsigned)((n_w1 + 255) / 256), 256>>>(w_ih1, w1_hi, w1_lo, n_w1);
    split_bf16_kernel<<<(unsigned)((n_xs + 255) / 256), 256>>>(xs, xs_hi, xs_lo, n_xs);

    // ---- layer 0 ----
    gemm_mma<<<gemm_grid, 256>>>(xs_hi, xs_lo, w0_hi, w0_lo, b_ih0, Ec);
    zero_h_kernel<<<(2 * Bc * Hc) / 256, 256>>>();
    gru_persist_mma<<<persist_grid, 128, PERSIST_SMEM>>>(w_hh0, b_hh0, out, 0);
    hy_copy_kernel<<<(2 * Bc * Hc) / 256, 256>>>(out, 0);

    // ---- layer 1 ----
    split_bf16_kernel<<<(unsigned)((n_h0 + 255) / 256), 256>>>(h0out, h0_hi, h0_lo, n_h0);
    gemm_mma<<<gemm_grid, 256>>>(h0_hi, h0_lo, w1_hi, w1_lo, b_ih1, 2 * Hc);
    zero_h_kernel<<<(2 * Bc * Hc) / 256, 256>>>();
    gru_persist_mma<<<persist_grid, 128, PERSIST_SMEM>>>(w_hh1, b_hh1, out, 1);
    hy_copy_kernel<<<(2 * Bc * Hc) / 256, 256>>>(out, 1);
}

// round 7
// speedup vs baseline: 2.9452x; 1.2891x over previous
#include <cuda_runtime.h>
#include <cuda_bf16.h>
#include <cstdint>
#include <math.h>

#define Bc 64
#define Tc 512
#define Ec 512
#define Hc 512
#define Gc 1536            // 3*H
#define M_TOK (Bc*Tc)      // 32768 tokens
#define HY_OFF ((size_t)Bc*Tc*2*Hc)
#define NBLK_GRP 32        // blocks per barrier group (dir x batch-half)

// ---------------- device scratch ----------------
__device__ float g_gx[(size_t)2*M_TOK*Gc];       // [dir][b*T+t][3H]
__device__ float g_h0out[(size_t)M_TOK*2*Hc];    // layer0 output [b][t][2H]

// h state as bf16 hi/lo split, layout [buf][dir][batch b][hidden j]
__device__ __nv_bfloat16 g_hAhi[2][2*Bc*Hc];
__device__ __nv_bfloat16 g_hAlo[2][2*Bc*Hc];

// bf16 split operands for gx GEMMs
__device__ __nv_bfloat16 g_xs_hi[(size_t)M_TOK*Ec],  g_xs_lo[(size_t)M_TOK*Ec];
__device__ __nv_bfloat16 g_h0_hi[(size_t)M_TOK*2*Hc], g_h0_lo[(size_t)M_TOK*2*Hc];
__device__ __nv_bfloat16 g_w0_hi[(size_t)2*Gc*Ec],   g_w0_lo[(size_t)2*Gc*Ec];
__device__ __nv_bfloat16 g_w1_hi[(size_t)2*Gc*2*Hc], g_w1_lo[(size_t)2*Gc*2*Hc];

// per-group barrier state (4 groups, padded to separate cache lines)
__device__ int g_bar_cnt[4 * 32];
__device__ volatile int g_bar_gen2[4 * 32];

// warp-mma helpers (base PTX, no 'a'-features)
#define LDSM4(r0, r1, r2, r3, addr) \
    asm volatile("ldmatrix.sync.aligned.m8n8.x4.shared.b16 {%0,%1,%2,%3}, [%4];" \
                 : "=r"(r0), "=r"(r1), "=r"(r2), "=r"(r3) : "r"(addr))

#define LDSM2(r0, r1, addr) \
    asm volatile("ldmatrix.sync.aligned.m8n8.x2.shared.b16 {%0,%1}, [%2];" \
                 : "=r"(r0), "=r"(r1) : "r"(addr))

#define MMA16816(d, a, b0, b1) \
    asm volatile("mma.sync.aligned.m16n8k16.row.col.f32.bf16.bf16.f32 " \
                 "{%0,%1,%2,%3}, {%4,%5,%6,%7}, {%8,%9}, {%0,%1,%2,%3};" \
                 : "+f"(d[0]), "+f"(d[1]), "+f"(d[2]), "+f"(d[3]) \
                 : "r"(a[0]), "r"(a[1]), "r"(a[2]), "r"(a[3]), "r"(b0), "r"(b1))

#define CP_ASYNC16(saddr, gptr) \
    asm volatile("cp.async.cg.shared.global [%0], [%1], 16;" \
                 :: "r"(saddr), "l"(gptr) : "memory")
#define CP_COMMIT() asm volatile("cp.async.commit_group;" ::: "memory")
#define CP_WAIT1()  asm volatile("cp.async.wait_group 1;" ::: "memory")
#define CP_WAIT0()  asm volatile("cp.async.wait_group 0;" ::: "memory")

__device__ __forceinline__ uint32_t smem_u32(const void* p) {
    uint32_t a;
    asm("{ .reg .u64 t; cvta.to.shared.u64 t, %1; cvt.u32.u64 %0, t; }" : "=r"(a) : "l"(p));
    return a;
}

// ---------------- bf16 split prep ----------------
__global__ void split_bf16_kernel(const float* __restrict__ src,
                                  __nv_bfloat16* __restrict__ hi,
                                  __nv_bfloat16* __restrict__ lo, size_t n) {
    size_t i = (size_t)blockIdx.x * blockDim.x + threadIdx.x;
    if (i >= n) return;
    float a = src[i];
    __nv_bfloat16 h = __float2bfloat16(a);
    hi[i] = h;
    lo[i] = __float2bfloat16(a - __bfloat162float(h));
}

// ---------------- zero hidden state (buf 0, both splits) ----------------
__global__ void zero_h_kernel() {
    int i = blockIdx.x * blockDim.x + threadIdx.x;   // 2*B*H = 65536
    g_hAhi[0][i] = __float2bfloat16(0.0f);
    g_hAlo[0][i] = __float2bfloat16(0.0f);
}

// ---------------- tensor-core gx GEMM (unchanged, proven R4-R6) ------------
#define KC 32
#define PITCH 40

__global__ void __launch_bounds__(256, 2)
gemm_mma(const __nv_bfloat16* __restrict__ Ahi, const __nv_bfloat16* __restrict__ Alo,
         const __nv_bfloat16* __restrict__ Whi, const __nv_bfloat16* __restrict__ Wlo,
         const float* __restrict__ bias, int K)
{
    __shared__ __nv_bfloat16 sAhi[128 * PITCH], sAlo[128 * PITCH];
    __shared__ __nv_bfloat16 sBhi[128 * PITCH], sBlo[128 * PITCH];

    int tid  = threadIdx.x;
    int wid  = tid >> 5, lane = tid & 31;
    int dir  = blockIdx.z;
    int n0   = blockIdx.x * 128;
    int m0   = blockIdx.y * 128;
    int wm   = wid >> 1;
    int wn   = wid & 1;

    const __nv_bfloat16* bhi = Whi + (size_t)dir * Gc * K;
    const __nv_bfloat16* blo = Wlo + (size_t)dir * Gc * K;
    float* C = g_gx + (size_t)dir * M_TOK * Gc;
    const float* bp = bias + dir * Gc;

    float acc[2][8][4];
#pragma unroll
    for (int i = 0; i < 2; i++)
#pragma unroll
        for (int j = 0; j < 8; j++)
#pragma unroll
            for (int q = 0; q < 4; q++) acc[i][j][q] = 0.0f;

    uint32_t uAhi = smem_u32(sAhi), uAlo = smem_u32(sAlo);
    uint32_t uBhi = smem_u32(sBhi), uBlo = smem_u32(sBlo);

    int a_row = (lane & 15);
    int a_col = (lane >> 4) * 8;
    int b_row = (lane & 7) + ((lane >> 4) & 1) * 8;
    int b_col = ((lane >> 3) & 1) * 8;

    const int nchunks = K / KC;
    for (int c = 0; c < nchunks; c++) {
        int k0 = c * KC;
        __syncthreads();
#pragma unroll
        for (int p = 0; p < 2; p++) {
            int idx = p * 256 + tid;
            int r   = idx >> 2;
            int c4  = idx & 3;
            size_t ga = (size_t)(m0 + r) * K + k0 + c4 * 8;
            size_t gb = (size_t)(n0 + r) * K + k0 + c4 * 8;
            int so = r * PITCH + c4 * 8;
            *(uint4*)&sAhi[so] = *(const uint4*)(Ahi + ga);
            *(uint4*)&sAlo[so] = *(const uint4*)(Alo + ga);
            *(uint4*)&sBhi[so] = *(const uint4*)(bhi + gb);
            *(uint4*)&sBlo[so] = *(const uint4*)(blo + gb);
        }
        __syncthreads();

#pragma unroll
        for (int kk = 0; kk < 2; kk++) {
            int k16 = kk * 16;
            uint32_t ahi[2][4], alo[2][4];
#pragma unroll
            for (int mt = 0; mt < 2; mt++) {
                uint32_t off = 2u * ((wm * 32 + mt * 16 + a_row) * PITCH + k16 + a_col);
                LDSM4(ahi[mt][0], ahi[mt][1], ahi[mt][2], ahi[mt][3], uAhi + off);
                LDSM4(alo[mt][0], alo[mt][1], alo[mt][2], alo[mt][3], uAlo + off);
            }
#pragma unroll
            for (int np = 0; np < 4; np++) {
                uint32_t off = 2u * ((wn * 64 + np * 16 + b_row) * PITCH + k16 + b_col);
                uint32_t bh0, bh1, bh2, bh3, bl0, bl1, bl2, bl3;
                LDSM4(bh0, bh1, bh2, bh3, uBhi + off);
                LDSM4(bl0, bl1, bl2, bl3, uBlo + off);
#pragma unroll
                for (int mt = 0; mt < 2; mt++) {
                    MMA16816(acc[mt][np * 2 + 0], ahi[mt], bh0, bh1);
                    MMA16816(acc[mt][np * 2 + 0], ahi[mt], bl0, bl1);
                    MMA16816(acc[mt][np * 2 + 0], alo[mt], bh0, bh1);
                    MMA16816(acc[mt][np * 2 + 1], ahi[mt], bh2, bh3);
                    MMA16816(acc[mt][np * 2 + 1], ahi[mt], bl2, bl3);
                    MMA16816(acc[mt][np * 2 + 1], alo[mt], bh2, bh3);
                }
            }
        }
    }

#pragma unroll
    for (int mt = 0; mt < 2; mt++) {
#pragma unroll
        for (int nt = 0; nt < 8; nt++) {
            int row = m0 + wm * 32 + mt * 16 + (lane >> 2);
            int col = n0 + wn * 64 + nt * 8 + (lane & 3) * 2;
            float b0 = bp[col], b1 = bp[col + 1];
            float2 v0 = make_float2(acc[mt][nt][0] + b0, acc[mt][nt][1] + b1);
            float2 v1 = make_float2(acc[mt][nt][2] + b0, acc[mt][nt][3] + b1);
            *(float2*)&C[(size_t)row * Gc + col]       = v0;
            *(float2*)&C[(size_t)(row + 8) * Gc + col] = v1;
        }
    }
}

// ---------------- persistent MMA recurrence (batch x j partition) ----------
// Grid (32 j-chunks, 2 batch-halves, 2 dirs), 128 threads.
// Block: units [j0,j0+16) -> 48 gate rows (gate-major r=g*16+jj), batches
// [b0,b0+32). gh = h @ Wslice^T, M=32, N=48, K=512, cp.async K-pipeline.
#define RPITCH 520
#define OFF_WHI 0
#define SZ_W    (48 * RPITCH * 2)
#define OFF_WLO (OFF_WHI + SZ_W)
#define OFF_HHI (OFF_WLO + SZ_W)
#define SZ_H    (32 * RPITCH * 2)
#define OFF_HLO (OFF_HHI + SZ_H)
#define OFF_G   (OFF_HLO + SZ_H)            // [48][40] floats
#define OFF_X   (OFF_G + 48 * 40 * 4)       // [32][16] floats
#define PERSIST_SMEM (OFF_X + 32 * 16 * 4)  // 176128 bytes

__global__ void __launch_bounds__(128, 1)
gru_persist_mma(const float* __restrict__ w_hh,
                const float* __restrict__ b_hh,
                float* __restrict__ out_l1,
                int layer)
{
    extern __shared__ char sm[];
    __nv_bfloat16* sWhi = (__nv_bfloat16*)(sm + OFF_WHI);
    __nv_bfloat16* sWlo = (__nv_bfloat16*)(sm + OFF_WLO);
    __nv_bfloat16* sHhi = (__nv_bfloat16*)(sm + OFF_HHI);
    __nv_bfloat16* sHlo = (__nv_bfloat16*)(sm + OFF_HLO);
    float* sG = (float*)(sm + OFF_G);    // [48 gate rows][40]
    float* sX = (float*)(sm + OFF_X);    // [32][16] h_new exchange

    int tid = threadIdx.x, lane = tid & 31, wid = tid >> 5;
    int dir   = blockIdx.z;
    int bhalf = blockIdx.y;
    int j0    = blockIdx.x * 16;
    int b0    = bhalf * 32;
    int grp   = (dir * 2 + bhalf) * 32;

    int wm = wid & 1;            // M-tile (16 batch rows)
    int wn2 = wid >> 1;          // N-half (24 gate rows)
    int nbase = wn2 * 24;
    int m_base = wm * 16;

    int jl = tid >> 3;           // 0..15 unit
    int bg = tid & 7;            // 0..7  batch group (4 each)
    int jglob = j0 + jl;

    int wb = tid >> 2;           // writer: batch 0..31
    int wj4 = (tid & 3) * 4;     // writer: j-quad

    // one-time: load + split W slice (48 rows, gate-major r = g*16 + jj)
    const float* W = w_hh + (size_t)dir * Gc * Hc;
    for (int idx = tid; idx < 48 * 512; idx += 128) {
        int r = idx >> 9, k = idx & 511;
        int gg = r >> 4, jj = r & 15;
        float w = W[(size_t)(gg * Hc + j0 + jj) * Hc + k];
        __nv_bfloat16 h = __float2bfloat16(w);
        sWhi[r * RPITCH + k] = h;
        sWlo[r * RPITCH + k] = __float2bfloat16(w - __bfloat162float(h));
    }
    float br = __ldg(&b_hh[dir * Gc + jglob]);
    float bz = __ldg(&b_hh[dir * Gc + Hc + jglob]);
    float bn = __ldg(&b_hh[dir * Gc + 2 * Hc + jglob]);

    const float* gx = g_gx + (size_t)dir * M_TOK * Gc;
    float* hs = (layer == 0) ? g_h0out : out_l1;

    uint32_t uWhi = smem_u32(sWhi), uWlo = smem_u32(sWlo);
    uint32_t uHhi = smem_u32(sHhi), uHlo = smem_u32(sHlo);

    int a_row = lane & 15, a_col = (lane >> 4) * 8;
    int b_row = (lane & 7) + ((lane >> 4) & 1) * 8, b_col = ((lane >> 3) & 1) * 8;
    int b_row2 = 16 + (lane & 7);

    int lgen = g_bar_gen2[grp];
    __syncthreads();

    // prefetch gx for s = 0
    float pgr[4], pgz[4], pgn[4];
    {
        int t0 = dir ? (Tc - 1) : 0;
#pragma unroll
        for (int q = 0; q < 4; q++) {
            int b = b0 + bg * 4 + q;
            size_t gb = ((size_t)b * Tc + t0) * Gc;
            pgr[q] = __ldg(&gx[gb + jglob]);
            pgz[q] = __ldg(&gx[gb + Hc + jglob]);
            pgn[q] = __ldg(&gx[gb + 2 * Hc + jglob]);
        }
    }

    for (int s = 0; s < Tc; s++) {
        int rbuf = s & 1;
        int t = dir ? (Tc - 1 - s) : s;
        const __nv_bfloat16* hAhi = g_hAhi[rbuf] + dir * Bc * Hc;
        const __nv_bfloat16* hAlo = g_hAlo[rbuf] + dir * Bc * Hc;
        __nv_bfloat16* wAhi = g_hAhi[rbuf ^ 1] + dir * Bc * Hc;
        __nv_bfloat16* wAlo = g_hAlo[rbuf ^ 1] + dir * Bc * Hc;

        float acc[3][4];
#pragma unroll
        for (int i = 0; i < 3; i++)
#pragma unroll
            for (int q = 0; q < 4; q++) acc[i][q] = 0.0f;

        // cp.async stage chunk 0 (cols 0..127)
#pragma unroll
        for (int p = 0; p < 8; p++) {
            int idx = tid + p * 128;            // 0..1023
            int split = idx >> 9;
            int rrow  = (idx >> 4) & 31;
            int c16   = idx & 15;
            const __nv_bfloat16* gsrc =
                (split ? hAlo : hAhi) + (size_t)(b0 + rrow) * Hc + c16 * 8;
            uint32_t sdst = (split ? uHlo : uHhi) + (rrow * RPITCH + c16 * 8) * 2;
            CP_ASYNC16(sdst, (const void*)gsrc);
        }
        CP_COMMIT();

#pragma unroll
        for (int c = 0; c < 4; c++) {
            if (c < 3) {
                int kc = (c + 1) * 128;
#pragma unroll
                for (int p = 0; p < 8; p++) {
                    int idx = tid + p * 128;
                    int split = idx >> 9;
                    int rrow  = (idx >> 4) & 31;
                    int c16   = idx & 15;
                    const __nv_bfloat16* gsrc =
                        (split ? hAlo : hAhi) + (size_t)(b0 + rrow) * Hc + kc + c16 * 8;
                    uint32_t sdst = (split ? uHlo : uHhi) + (rrow * RPITCH + kc + c16 * 8) * 2;
                    CP_ASYNC16(sdst, (const void*)gsrc);
                }
                CP_COMMIT();
                CP_WAIT1();
            } else {
                CP_WAIT0();
            }
            __syncthreads();

            // MMA on chunk c: k16 in [c*8, c*8+8)
#pragma unroll
            for (int kk = 0; kk < 8; kk++) {
                int k16 = c * 8 + kk;
                uint32_t offA = (uint32_t)(((m_base + a_row) * RPITCH + k16 * 16 + a_col) * 2);
                uint32_t ahi[4], alo[4];
                LDSM4(ahi[0], ahi[1], ahi[2], ahi[3], uHhi + offA);
                LDSM4(alo[0], alo[1], alo[2], alo[3], uHlo + offA);

                uint32_t offB = (uint32_t)(((nbase + b_row) * RPITCH + k16 * 16 + b_col) * 2);
                uint32_t bh0, bh1, bh2, bh3, bl0, bl1, bl2, bl3;
                LDSM4(bh0, bh1, bh2, bh3, uWhi + offB);
                LDSM4(bl0, bl1, bl2, bl3, uWlo + offB);
                MMA16816(acc[0], ahi, bh0, bh1);
                MMA16816(acc[0], ahi, bl0, bl1);
                MMA16816(acc[0], alo, bh0, bh1);
                MMA16816(acc[1], ahi, bh2, bh3);
                MMA16816(acc[1], ahi, bl2, bl3);
                MMA16816(acc[1], alo, bh2, bh3);

                uint32_t offB2 = (uint32_t)(((nbase + b_row2) * RPITCH + k16 * 16 + b_col) * 2);
                uint32_t ch0, ch1, cl0, cl1;
                LDSM2(ch0, ch1, uWhi + offB2);
                LDSM2(cl0, cl1, uWlo + offB2);
                MMA16816(acc[2], ahi, ch0, ch1);
                MMA16816(acc[2], ahi, cl0, cl1);
                MMA16816(acc[2], alo, ch0, ch1);
            }
        }

        // dump gh to sG[gate row][batch row]
#pragma unroll
        for (int nt = 0; nt < 3; nt++) {
            int c0 = nbase + nt * 8 + (lane & 3) * 2;
            int r0 = m_base + (lane >> 2);
            sG[c0 * 40 + r0]             = acc[nt][0];
            sG[(c0 + 1) * 40 + r0]       = acc[nt][1];
            sG[c0 * 40 + r0 + 8]         = acc[nt][2];
            sG[(c0 + 1) * 40 + r0 + 8]   = acc[nt][3];
        }
        __syncthreads();

        // gate math: thread (jl, bg) -> unit jglob, local batches bg*4..+3
#pragma unroll
        for (int q = 0; q < 4; q++) {
            int lb = bg * 4 + q;
            float ghr = sG[jl * 40 + lb];
            float ghz = sG[(16 + jl) * 40 + lb];
            float ghn = sG[(32 + jl) * 40 + lb];
            float hp = __bfloat162float(sHhi[lb * RPITCH + jglob])
                     + __bfloat162float(sHlo[lb * RPITCH + jglob]);
            float rr = 1.0f / (1.0f + __expf(-(pgr[q] + ghr + br)));
            float zz = 1.0f / (1.0f + __expf(-(pgz[q] + ghz + bz)));
            float xa = pgn[q] + rr * (ghn + bn);
            float e2 = __expf(2.0f * xa);
            float nn = 1.0f - __fdividef(2.0f, e2 + 1.0f);
            float hv = (1.0f - zz) * nn + zz * hp;
            sX[lb * 16 + jl] = hv;
        }
        __syncthreads();

        // coalesced h_new global write: thread -> (batch wb, j-quad wj4)
        {
            float v0 = sX[wb * 16 + wj4 + 0];
            float v1 = sX[wb * 16 + wj4 + 1];
            float v2 = sX[wb * 16 + wj4 + 2];
            float v3 = sX[wb * 16 + wj4 + 3];
            __nv_bfloat16 h0 = __float2bfloat16(v0), h1 = __float2bfloat16(v1);
            __nv_bfloat16 h2 = __float2bfloat16(v2), h3 = __float2bfloat16(v3);
            __nv_bfloat162 hi01 = {h0, h1}, hi23 = {h2, h3};
            __nv_bfloat162 lo01 = {__float2bfloat16(v0 - __bfloat162float(h0)),
                                   __float2bfloat16(v1 - __bfloat162float(h1))};
            __nv_bfloat162 lo23 = {__float2bfloat16(v2 - __bfloat162float(h2)),
                                   __float2bfloat16(v3 - __bfloat162float(h3))};
            size_t base = (size_t)(b0 + wb) * Hc + j0 + wj4;
            *(__nv_bfloat162*)(wAhi + base)     = hi01;
            *(__nv_bfloat162*)(wAhi + base + 2) = hi23;
            *(__nv_bfloat162*)(wAlo + base)     = lo01;
            *(__nv_bfloat162*)(wAlo + base + 2) = lo23;
        }
        __threadfence();
        __syncthreads();

        int was_last = 0;
        if (s != Tc - 1 && tid == 0) {
            was_last = (atomicAdd(&g_bar_cnt[grp], 1) == NBLK_GRP - 1);
        }

        // off-critical-path: hs output + next-step gx prefetch
        {
            float4 xv = make_float4(sX[wb * 16 + wj4], sX[wb * 16 + wj4 + 1],
                                    sX[wb * 16 + wj4 + 2], sX[wb * 16 + wj4 + 3]);
            *(float4*)&hs[((size_t)(b0 + wb) * Tc + t) * (2 * Hc) + dir * Hc + j0 + wj4] = xv;
        }
        {
            int sn = (s + 1 < Tc) ? s + 1 : s;
            int tn = dir ? (Tc - 1 - sn) : sn;
#pragma unroll
            for (int q = 0; q < 4; q++) {
                int b = b0 + bg * 4 + q;
                size_t gb = ((size_t)b * Tc + tn) * Gc;
                pgr[q] = __ldg(&gx[gb + jglob]);
                pgz[q] = __ldg(&gx[gb + Hc + jglob]);
                pgn[q] = __ldg(&gx[gb + 2 * Hc + jglob]);
            }
        }

        if (s != Tc - 1) {
            if (tid == 0) {
                if (was_last) {
                    g_bar_cnt[grp] = 0;
                    __threadfence();
                    g_bar_gen2[grp] = lgen + 1;
                } else {
                    while (g_bar_gen2[grp] == lgen) { }
                }
                lgen = lgen + 1;
            }
            __syncthreads();
        }
    }
}

// ---------------- copy final hidden states ----------------
__global__ void hy_copy_kernel(float* __restrict__ d_out, int layer) {
    int i = blockIdx.x * blockDim.x + threadIdx.x;   // 0..65535
    int dir = i >> 15;
    int rem = i & 32767;                              // = b*512 + j
    d_out[HY_OFF + (size_t)(2 * layer + dir) * Bc * Hc + rem] =
        __bfloat162float(g_hAhi[0][dir * Bc * Hc + rem]) +
        __bfloat162float(g_hAlo[0][dir * Bc * Hc + rem]);
}

// ---------------- launch ----------------
extern "C" void kernel_launch(void* const* d_in, const int* in_sizes, int n_in,
                              void* d_out, int out_size)
{
    const float* xs    = (const float*)d_in[0];
    const float* w_ih0 = (const float*)d_in[1];
    const float* w_hh0 = (const float*)d_in[2];
    const float* b_ih0 = (const float*)d_in[3];
    const float* b_hh0 = (const float*)d_in[4];
    const float* w_ih1 = (const float*)d_in[5];
    const float* w_hh1 = (const float*)d_in[6];
    const float* b_ih1 = (const float*)d_in[7];
    const float* b_hh1 = (const float*)d_in[8];
    float* out = (float*)d_out;

    cudaFuncSetAttribute(gru_persist_mma,
                         cudaFuncAttributeMaxDynamicSharedMemorySize, PERSIST_SMEM);

    __nv_bfloat16 *xs_hi, *xs_lo, *h0_hi, *h0_lo, *w0_hi, *w0_lo, *w1_hi, *w1_lo;
    cudaGetSymbolAddress((void**)&xs_hi, g_xs_hi);
    cudaGetSymbolAddress((void**)&xs_lo, g_xs_lo);
    cudaGetSymbolAddress((void**)&h0_hi, g_h0_hi);
    cudaGetSymbolAddress((void**)&h0_lo, g_h0_lo);
    cudaGetSymbolAddress((void**)&w0_hi, g_w0_hi);
    cudaGetSymbolAddress((void**)&w0_lo, g_w0_lo);
    cudaGetSymbolAddress((void**)&w1_hi, g_w1_hi);
    cudaGetSymbolAddress((void**)&w1_lo, g_w1_lo);
    float* h0out;
    cudaGetSymbolAddress((void**)&h0out, g_h0out);

    dim3 gemm_grid(Gc / 128, M_TOK / 128, 2);   // (12, 256, 2)
    dim3 persist_grid(32, 2, 2);                // 128 blocks

    size_t n_w0 = (size_t)2 * Gc * Ec;
    size_t n_w1 = (size_t)2 * Gc * 2 * Hc;
    size_t n_xs = (size_t)M_TOK * Ec;
    size_t n_h0 = (size_t)M_TOK * 2 * Hc;

    split_bf16_kernel<<<(unsigned)((n_w0 + 255) / 256), 256>>>(w_ih0, w0_hi, w0_lo, n_w0);
    split_bf16_kernel<<<(unsigned)((n_w1 + 255) / 256), 256>>>(w_ih1, w1_hi, w1_lo, n_w1);
    split_bf16_kernel<<<(unsigned)((n_xs + 255) / 256), 256>>>(xs, xs_hi, xs_lo, n_xs);

    // ---- layer 0 ----
    gemm_mma<<<gemm_grid, 256>>>(xs_hi, xs_lo, w0_hi, w0_lo, b_ih0, Ec);
    zero_h_kernel<<<(2 * Bc * Hc) / 256, 256>>>();
    gru_persist_mma<<<persist_grid, 128, PERSIST_SMEM>>>(w_hh0, b_hh0, out, 0);
    hy_copy_kernel<<<(2 * Bc * Hc) / 256, 256>>>(out, 0);

    // ---- layer 1 ----
    split_bf16_kernel<<<(unsigned)((n_h0 + 255) / 256), 256>>>(h0out, h0_hi, h0_lo, n_h0);
    gemm_mma<<<gemm_grid, 256>>>(h0_hi, h0_lo, w1_hi, w1_lo, b_ih1, 2 * Hc);
    zero_h_kernel<<<(2 * Bc * Hc) / 256, 256>>>();
    gru_persist_mma<<<persist_grid, 128, PERSIST_SMEM>>>(w_hh1, b_hh1, out, 1);
    hy_copy_kernel<<<(2 * Bc * Hc) / 256, 256>>>(out, 1);
}

// round 8
// speedup vs baseline: 2.9665x; 1.0072x over previous
#include <cuda_runtime.h>
#include <cuda_bf16.h>
#include <cstdint>
#include <math.h>

#define Bc 64
#define Tc 512
#define Ec 512
#define Hc 512
#define Gc 1536            // 3*H
#define M_TOK (Bc*Tc)      // 32768 tokens
#define HY_OFF ((size_t)Bc*Tc*2*Hc)
#define NBLK_GRP 32        // blocks per barrier group (dir x batch-half)

// ---------------- device scratch ----------------
// gx layout: [dir][t][bhalf][jc(32)][g(3)][b_local(32)][jl(16)]
__device__ float g_gx[(size_t)2*M_TOK*Gc];
__device__ float g_h0out[(size_t)M_TOK*2*Hc];    // layer0 output [b][t][2H]

// h state as bf16 hi/lo split, layout [buf][dir][batch b][hidden j]
__device__ __nv_bfloat16 g_hAhi[2][2*Bc*Hc];
__device__ __nv_bfloat16 g_hAlo[2][2*Bc*Hc];

// bf16 split operands for gx GEMMs
__device__ __nv_bfloat16 g_xs_hi[(size_t)M_TOK*Ec],  g_xs_lo[(size_t)M_TOK*Ec];
__device__ __nv_bfloat16 g_h0_hi[(size_t)M_TOK*2*Hc], g_h0_lo[(size_t)M_TOK*2*Hc];
__device__ __nv_bfloat16 g_w0_hi[(size_t)2*Gc*Ec],   g_w0_lo[(size_t)2*Gc*Ec];
__device__ __nv_bfloat16 g_w1_hi[(size_t)2*Gc*2*Hc], g_w1_lo[(size_t)2*Gc*2*Hc];

// per-group barrier state (4 groups, padded to separate cache lines)
__device__ int g_bar_cnt[4 * 32];
__device__ volatile int g_bar_gen2[4 * 32];

// warp-mma helpers (base PTX, no 'a'-features)
#define LDSM4(r0, r1, r2, r3, addr) \
    asm volatile("ldmatrix.sync.aligned.m8n8.x4.shared.b16 {%0,%1,%2,%3}, [%4];" \
                 : "=r"(r0), "=r"(r1), "=r"(r2), "=r"(r3) : "r"(addr))

#define LDSM2(r0, r1, addr) \
    asm volatile("ldmatrix.sync.aligned.m8n8.x2.shared.b16 {%0,%1}, [%2];" \
                 : "=r"(r0), "=r"(r1) : "r"(addr))

#define MMA16816(d, a, b0, b1) \
    asm volatile("mma.sync.aligned.m16n8k16.row.col.f32.bf16.bf16.f32 " \
                 "{%0,%1,%2,%3}, {%4,%5,%6,%7}, {%8,%9}, {%0,%1,%2,%3};" \
                 : "+f"(d[0]), "+f"(d[1]), "+f"(d[2]), "+f"(d[3]) \
                 : "r"(a[0]), "r"(a[1]), "r"(a[2]), "r"(a[3]), "r"(b0), "r"(b1))

#define CP_ASYNC16(saddr, gptr) \
    asm volatile("cp.async.cg.shared.global [%0], [%1], 16;" \
                 :: "r"(saddr), "l"(gptr) : "memory")
#define CP_COMMIT() asm volatile("cp.async.commit_group;" ::: "memory")
#define CP_WAIT1()  asm volatile("cp.async.wait_group 1;" ::: "memory")
#define CP_WAIT0()  asm volatile("cp.async.wait_group 0;" ::: "memory")

__device__ __forceinline__ uint32_t smem_u32(const void* p) {
    uint32_t a;
    asm("{ .reg .u64 t; cvta.to.shared.u64 t, %1; cvt.u32.u64 %0, t; }" : "=r"(a) : "l"(p));
    return a;
}

// ---------------- bf16 split prep ----------------
__global__ void split_bf16_kernel(const float* __restrict__ src,
                                  __nv_bfloat16* __restrict__ hi,
                                  __nv_bfloat16* __restrict__ lo, size_t n) {
    size_t i = (size_t)blockIdx.x * blockDim.x + threadIdx.x;
    if (i >= n) return;
    float a = src[i];
    __nv_bfloat16 h = __float2bfloat16(a);
    hi[i] = h;
    lo[i] = __float2bfloat16(a - __bfloat162float(h));
}

// ---------------- zero hidden state (buf 0, both splits) ----------------
__global__ void zero_h_kernel() {
    int i = blockIdx.x * blockDim.x + threadIdx.x;   // 2*B*H = 65536
    g_hAhi[0][i] = __float2bfloat16(0.0f);
    g_hAlo[0][i] = __float2bfloat16(0.0f);
}

// ---------------- tensor-core gx GEMM (core proven R4-R7; epilogue re-laid) -
#define KC 32
#define PITCH 40

__global__ void __launch_bounds__(256, 2)
gemm_mma(const __nv_bfloat16* __restrict__ Ahi, const __nv_bfloat16* __restrict__ Alo,
         const __nv_bfloat16* __restrict__ Whi, const __nv_bfloat16* __restrict__ Wlo,
         const float* __restrict__ bias, int K)
{
    __shared__ __nv_bfloat16 sAhi[128 * PITCH], sAlo[128 * PITCH];
    __shared__ __nv_bfloat16 sBhi[128 * PITCH], sBlo[128 * PITCH];

    int tid  = threadIdx.x;
    int wid  = tid >> 5, lane = tid & 31;
    int dir  = blockIdx.z;
    int n0   = blockIdx.x * 128;
    int m0   = blockIdx.y * 128;
    int wm   = wid >> 1;
    int wn   = wid & 1;

    const __nv_bfloat16* bhi = Whi + (size_t)dir * Gc * K;
    const __nv_bfloat16* blo = Wlo + (size_t)dir * Gc * K;
    float* C = g_gx + (size_t)dir * M_TOK * Gc;
    const float* bp = bias + dir * Gc;

    float acc[2][8][4];
#pragma unroll
    for (int i = 0; i < 2; i++)
#pragma unroll
        for (int j = 0; j < 8; j++)
#pragma unroll
            for (int q = 0; q < 4; q++) acc[i][j][q] = 0.0f;

    uint32_t uAhi = smem_u32(sAhi), uAlo = smem_u32(sAlo);
    uint32_t uBhi = smem_u32(sBhi), uBlo = smem_u32(sBlo);

    int a_row = (lane & 15);
    int a_col = (lane >> 4) * 8;
    int b_row = (lane & 7) + ((lane >> 4) & 1) * 8;
    int b_col = ((lane >> 3) & 1) * 8;

    const int nchunks = K / KC;
    for (int c = 0; c < nchunks; c++) {
        int k0 = c * KC;
        __syncthreads();
#pragma unroll
        for (int p = 0; p < 2; p++) {
            int idx = p * 256 + tid;
            int r   = idx >> 2;
            int c4  = idx & 3;
            size_t ga = (size_t)(m0 + r) * K + k0 + c4 * 8;
            size_t gb = (size_t)(n0 + r) * K + k0 + c4 * 8;
            int so = r * PITCH + c4 * 8;
            *(uint4*)&sAhi[so] = *(const uint4*)(Ahi + ga);
            *(uint4*)&sAlo[so] = *(const uint4*)(Alo + ga);
            *(uint4*)&sBhi[so] = *(const uint4*)(bhi + gb);
            *(uint4*)&sBlo[so] = *(const uint4*)(blo + gb);
        }
        __syncthreads();

#pragma unroll
        for (int kk = 0; kk < 2; kk++) {
            int k16 = kk * 16;
            uint32_t ahi[2][4], alo[2][4];
#pragma unroll
            for (int mt = 0; mt < 2; mt++) {
                uint32_t off = 2u * ((wm * 32 + mt * 16 + a_row) * PITCH + k16 + a_col);
                LDSM4(ahi[mt][0], ahi[mt][1], ahi[mt][2], ahi[mt][3], uAhi + off);
                LDSM4(alo[mt][0], alo[mt][1], alo[mt][2], alo[mt][3], uAlo + off);
            }
#pragma unroll
            for (int np = 0; np < 4; np++) {
                uint32_t off = 2u * ((wn * 64 + np * 16 + b_row) * PITCH + k16 + b_col);
                uint32_t bh0, bh1, bh2, bh3, bl0, bl1, bl2, bl3;
                LDSM4(bh0, bh1, bh2, bh3, uBhi + off);
                LDSM4(bl0, bl1, bl2, bl3, uBlo + off);
#pragma unroll
                for (int mt = 0; mt < 2; mt++) {
                    MMA16816(acc[mt][np * 2 + 0], ahi[mt], bh0, bh1);
                    MMA16816(acc[mt][np * 2 + 0], ahi[mt], bl0, bl1);
                    MMA16816(acc[mt][np * 2 + 0], alo[mt], bh0, bh1);
                    MMA16816(acc[mt][np * 2 + 1], ahi[mt], bh2, bh3);
                    MMA16816(acc[mt][np * 2 + 1], ahi[mt], bl2, bl3);
                    MMA16816(acc[mt][np * 2 + 1], alo[mt], bh2, bh3);
                }
            }
        }
    }

    // epilogue: write to recurrence-friendly gx layout
    // addr = t*98304 + bhalf*49152 + jc*1536 + g*512 + b_local*16 + jl
#pragma unroll
    for (int mt = 0; mt < 2; mt++) {
#pragma unroll
        for (int nt = 0; nt < 8; nt++) {
            int row = m0 + wm * 32 + mt * 16 + (lane >> 2);
            int col = n0 + wn * 64 + nt * 8 + (lane & 3) * 2;
            float b0 = bp[col], b1 = bp[col + 1];
            int g = col >> 9, j = col & 511;
            int jc = j >> 4, jl = j & 15;
#pragma unroll
            for (int half = 0; half < 2; half++) {
                int r = row + half * 8;
                int bb = r >> 9, tt = r & 511;
                size_t addr = (size_t)tt * 98304 + (size_t)(bb >> 5) * 49152
                            + jc * 1536 + g * 512 + (bb & 31) * 16 + jl;
                float2 v = half ? make_float2(acc[mt][nt][2] + b0, acc[mt][nt][3] + b1)
                                : make_float2(acc[mt][nt][0] + b0, acc[mt][nt][1] + b1);
                *(float2*)&C[addr] = v;
            }
        }
    }
}

// ---------------- persistent MMA recurrence ----------
// Grid (32 j-chunks, 2 batch-halves, 2 dirs), 128 threads.
// Block: units [j0,j0+16) -> 48 gate rows, batches [b0,b0+32).
// gh = h @ Wslice^T, M=32, N=48, K=512; 2-chunk cp.async pipeline; gx slice
// contiguous per (block, step).
#define RPITCH 520
#define PG 41
#define OFF_WHI 0
#define SZ_W    (48 * RPITCH * 2)
#define OFF_WLO (OFF_WHI + SZ_W)
#define OFF_HHI (OFF_WLO + SZ_W)
#define SZ_H    (32 * RPITCH * 2)
#define OFF_HLO (OFF_HHI + SZ_H)
#define OFF_G   (OFF_HLO + SZ_H)            // [48][41] floats = 7872B
#define OFF_GX  (OFF_G + 48 * PG * 4)       // [3][32][16] floats = 6144B
#define OFF_X   (OFF_GX + 6144)             // [32][16] floats = 2048B
#define PERSIST_SMEM (OFF_X + 2048)         // 182464 bytes

__global__ void __launch_bounds__(128, 1)
gru_persist_mma(const float* __restrict__ w_hh,
                const float* __restrict__ b_hh,
                float* __restrict__ out_l1,
                int layer)
{
    extern __shared__ char sm[];
    __nv_bfloat16* sWhi = (__nv_bfloat16*)(sm + OFF_WHI);
    __nv_bfloat16* sWlo = (__nv_bfloat16*)(sm + OFF_WLO);
    __nv_bfloat16* sHhi = (__nv_bfloat16*)(sm + OFF_HHI);
    __nv_bfloat16* sHlo = (__nv_bfloat16*)(sm + OFF_HLO);
    float* sG  = (float*)(sm + OFF_G);    // [48 gate rows][41]
    float* sGX = (float*)(sm + OFF_GX);   // [3][32][16]
    float* sX  = (float*)(sm + OFF_X);    // [32][16] h_new exchange

    int tid = threadIdx.x, lane = tid & 31, wid = tid >> 5;
    int dir   = blockIdx.z;
    int bhalf = blockIdx.y;
    int j0    = blockIdx.x * 16;
    int b0    = bhalf * 32;
    int grp   = (dir * 2 + bhalf) * 32;

    int wm = wid & 1;            // M-tile (16 batch rows)
    int wn2 = wid >> 1;          // N-half (24 gate rows)
    int nbase = wn2 * 24;
    int m_base = wm * 16;

    int jl = tid & 15;           // unit (lane-consecutive)
    int bg = tid >> 4;           // 0..7 batch group (4 each)
    int jglob = j0 + jl;

    int wb = tid >> 2;           // writer: batch 0..31
    int wj4 = (tid & 3) * 4;     // writer: j-quad

    // one-time: load + split W slice (48 rows, gate-major r = g*16 + jj)
    const float* W = w_hh + (size_t)dir * Gc * Hc;
    for (int idx = tid; idx < 48 * 512; idx += 128) {
        int r = idx >> 9, k = idx & 511;
        int gg = r >> 4, jj = r & 15;
        float w = W[(size_t)(gg * Hc + j0 + jj) * Hc + k];
        __nv_bfloat16 h = __float2bfloat16(w);
        sWhi[r * RPITCH + k] = h;
        sWlo[r * RPITCH + k] = __float2bfloat16(w - __bfloat162float(h));
    }
    float br = __ldg(&b_hh[dir * Gc + jglob]);
    float bz = __ldg(&b_hh[dir * Gc + Hc + jglob]);
    float bn = __ldg(&b_hh[dir * Gc + 2 * Hc + jglob]);

    // gx slice for this block: contiguous 1536 floats per step
    const float* gxblk = g_gx + (size_t)dir * M_TOK * Gc
                       + (size_t)bhalf * 49152 + (size_t)blockIdx.x * 1536;
    float* hs = (layer == 0) ? g_h0out : out_l1;

    uint32_t uWhi = smem_u32(sWhi), uWlo = smem_u32(sWlo);
    uint32_t uHhi = smem_u32(sHhi), uHlo = smem_u32(sHlo);
    uint32_t uGX  = smem_u32(sGX);

    int a_row = lane & 15, a_col = (lane >> 4) * 8;
    int b_row = (lane & 7) + ((lane >> 4) & 1) * 8, b_col = ((lane >> 3) & 1) * 8;
    int b_row2 = 16 + (lane & 7);

    int lgen = g_bar_gen2[grp];
    __syncthreads();

    for (int s = 0; s < Tc; s++) {
        int rbuf = s & 1;
        int t = dir ? (Tc - 1 - s) : s;
        const __nv_bfloat16* hAhi = g_hAhi[rbuf] + dir * Bc * Hc;
        const __nv_bfloat16* hAlo = g_hAlo[rbuf] + dir * Bc * Hc;
        __nv_bfloat16* wAhi = g_hAhi[rbuf ^ 1] + dir * Bc * Hc;
        __nv_bfloat16* wAlo = g_hAlo[rbuf ^ 1] + dir * Bc * Hc;

        // chunk 0: h cols [0,256) both splits + gx slice
#pragma unroll
        for (int p = 0; p < 16; p++) {
            int idx = tid + p * 128;            // 0..2047
            int split = idx >> 10;
            int rrow  = (idx >> 5) & 31;
            int c16   = idx & 31;
            const __nv_bfloat16* gsrc =
                (split ? hAlo : hAhi) + (size_t)(b0 + rrow) * Hc + c16 * 8;
            uint32_t sdst = (split ? uHlo : uHhi) + (rrow * RPITCH + c16 * 8) * 2;
            CP_ASYNC16(sdst, (const void*)gsrc);
        }
        {
            const float* gxt = gxblk + (size_t)t * 98304;
#pragma unroll
            for (int p = 0; p < 3; p++) {
                int idx = tid + p * 128;        // 0..383
                CP_ASYNC16(uGX + idx * 16, (const void*)(gxt + idx * 4));
            }
        }
        CP_COMMIT();

        // chunk 1: h cols [256,512)
#pragma unroll
        for (int p = 0; p < 16; p++) {
            int idx = tid + p * 128;
            int split = idx >> 10;
            int rrow  = (idx >> 5) & 31;
            int c16   = idx & 31;
            const __nv_bfloat16* gsrc =
                (split ? hAlo : hAhi) + (size_t)(b0 + rrow) * Hc + 256 + c16 * 8;
            uint32_t sdst = (split ? uHlo : uHhi) + (rrow * RPITCH + 256 + c16 * 8) * 2;
            CP_ASYNC16(sdst, (const void*)gsrc);
        }
        CP_COMMIT();

        float acc[3][4];
#pragma unroll
        for (int i = 0; i < 3; i++)
#pragma unroll
            for (int q = 0; q < 4; q++) acc[i][q] = 0.0f;

#pragma unroll
        for (int c = 0; c < 2; c++) {
            if (c == 0) CP_WAIT1(); else CP_WAIT0();
            __syncthreads();
#pragma unroll
            for (int kk = 0; kk < 16; kk++) {
                int k16 = c * 16 + kk;
                uint32_t offA = (uint32_t)(((m_base + a_row) * RPITCH + k16 * 16 + a_col) * 2);
                uint32_t ahi[4], alo[4];
                LDSM4(ahi[0], ahi[1], ahi[2], ahi[3], uHhi + offA);
                LDSM4(alo[0], alo[1], alo[2], alo[3], uHlo + offA);

                uint32_t offB = (uint32_t)(((nbase + b_row) * RPITCH + k16 * 16 + b_col) * 2);
                uint32_t bh0, bh1, bh2, bh3, bl0, bl1, bl2, bl3;
                LDSM4(bh0, bh1, bh2, bh3, uWhi + offB);
                LDSM4(bl0, bl1, bl2, bl3, uWlo + offB);
                MMA16816(acc[0], ahi, bh0, bh1);
                MMA16816(acc[0], ahi, bl0, bl1);
                MMA16816(acc[0], alo, bh0, bh1);
                MMA16816(acc[1], ahi, bh2, bh3);
                MMA16816(acc[1], ahi, bl2, bl3);
                MMA16816(acc[1], alo, bh2, bh3);

                uint32_t offB2 = (uint32_t)(((nbase + b_row2) * RPITCH + k16 * 16 + b_col) * 2);
                uint32_t ch0, ch1, cl0, cl1;
                LDSM2(ch0, ch1, uWhi + offB2);
                LDSM2(cl0, cl1, uWlo + offB2);
                MMA16816(acc[2], ahi, ch0, ch1);
                MMA16816(acc[2], ahi, cl0, cl1);
                MMA16816(acc[2], alo, ch0, ch1);
            }
        }

        // dump gh to sG[gate row][batch row]
#pragma unroll
        for (int nt = 0; nt < 3; nt++) {
            int c0 = nbase + nt * 8 + (lane & 3) * 2;
            int r0 = m_base + (lane >> 2);
            sG[c0 * PG + r0]           = acc[nt][0];
            sG[(c0 + 1) * PG + r0]     = acc[nt][1];
            sG[c0 * PG + r0 + 8]       = acc[nt][2];
            sG[(c0 + 1) * PG + r0 + 8] = acc[nt][3];
        }
        __syncthreads();

        // gate math: thread (jl, bg) -> unit jglob, local batches bg*4..+3
#pragma unroll
        for (int q = 0; q < 4; q++) {
            int lb = bg * 4 + q;
            float ghr = sG[jl * PG + lb];
            float ghz = sG[(16 + jl) * PG + lb];
            float ghn = sG[(32 + jl) * PG + lb];
            float gr = sGX[lb * 16 + jl];
            float gz = sGX[512 + lb * 16 + jl];
            float gn = sGX[1024 + lb * 16 + jl];
            float hp = __bfloat162float(sHhi[lb * RPITCH + jglob])
                     + __bfloat162float(sHlo[lb * RPITCH + jglob]);
            float rr = 1.0f / (1.0f + __expf(-(gr + ghr + br)));
            float zz = 1.0f / (1.0f + __expf(-(gz + ghz + bz)));
            float xa = gn + rr * (ghn + bn);
            float e2 = __expf(2.0f * xa);
            float nn = 1.0f - __fdividef(2.0f, e2 + 1.0f);
            float hv = (1.0f - zz) * nn + zz * hp;
            sX[lb * 16 + jl] = hv;
        }
        __syncthreads();

        // coalesced h_new global write: thread -> (batch wb, j-quad wj4)
        {
            float v0 = sX[wb * 16 + wj4 + 0];
            float v1 = sX[wb * 16 + wj4 + 1];
            float v2 = sX[wb * 16 + wj4 + 2];
            float v3 = sX[wb * 16 + wj4 + 3];
            __nv_bfloat16 h0 = __float2bfloat16(v0), h1 = __float2bfloat16(v1);
            __nv_bfloat16 h2 = __float2bfloat16(v2), h3 = __float2bfloat16(v3);
            __nv_bfloat162 hi01 = {h0, h1}, hi23 = {h2, h3};
            __nv_bfloat162 lo01 = {__float2bfloat16(v0 - __bfloat162float(h0)),
                                   __float2bfloat16(v1 - __bfloat162float(h1))};
            __nv_bfloat162 lo23 = {__float2bfloat16(v2 - __bfloat162float(h2)),
                                   __float2bfloat16(v3 - __bfloat162float(h3))};
            size_t base = (size_t)(b0 + wb) * Hc + j0 + wj4;
            *(__nv_bfloat162*)(wAhi + base)     = hi01;
            *(__nv_bfloat162*)(wAhi + base + 2) = hi23;
            *(__nv_bfloat162*)(wAlo + base)     = lo01;
            *(__nv_bfloat162*)(wAlo + base + 2) = lo23;
        }
        __syncthreads();

        // release: tid0-only gpu fence (cumulative over block via the sync)
        int was_last = 0;
        if (s != Tc - 1 && tid == 0) {
            __threadfence();
            was_last = (atomicAdd(&g_bar_cnt[grp], 1) == NBLK_GRP - 1);
        }

        // off-critical-path: hs output (coalesced float4 via sX)
        {
            float4 xv = make_float4(sX[wb * 16 + wj4], sX[wb * 16 + wj4 + 1],
                                    sX[wb * 16 + wj4 + 2], sX[wb * 16 + wj4 + 3]);
            *(float4*)&hs[((size_t)(b0 + wb) * Tc + t) * (2 * Hc) + dir * Hc + j0 + wj4] = xv;
        }

        if (s != Tc - 1) {
            if (tid == 0) {
                if (was_last) {
                    g_bar_cnt[grp] = 0;
                    __threadfence();
                    g_bar_gen2[grp] = lgen + 1;
                } else {
                    while (g_bar_gen2[grp] == lgen) { }
                }
                lgen = lgen + 1;
            }
            __syncthreads();
        }
    }
}

// ---------------- copy final hidden states ----------------
__global__ void hy_copy_kernel(float* __restrict__ d_out, int layer) {
    int i = blockIdx.x * blockDim.x + threadIdx.x;   // 0..65535
    int dir = i >> 15;
    int rem = i & 32767;                              // = b*512 + j
    d_out[HY_OFF + (size_t)(2 * layer + dir) * Bc * Hc + rem] =
        __bfloat162float(g_hAhi[0][dir * Bc * Hc + rem]) +
        __bfloat162float(g_hAlo[0][dir * Bc * Hc + rem]);
}

// ---------------- launch ----------------
extern "C" void kernel_launch(void* const* d_in, const int* in_sizes, int n_in,
                              void* d_out, int out_size)
{
    const float* xs    = (const float*)d_in[0];
    const float* w_ih0 = (const float*)d_in[1];
    const float* w_hh0 = (const float*)d_in[2];
    const float* b_ih0 = (const float*)d_in[3];
    const float* b_hh0 = (const float*)d_in[4];
    const float* w_ih1 = (const float*)d_in[5];
    const float* w_hh1 = (const float*)d_in[6];
    const float* b_ih1 = (const float*)d_in[7];
    const float* b_hh1 = (const float*)d_in[8];
    float* out = (float*)d_out;

    cudaFuncSetAttribute(gru_persist_mma,
                         cudaFuncAttributeMaxDynamicSharedMemorySize, PERSIST_SMEM);

    __nv_bfloat16 *xs_hi, *xs_lo, *h0_hi, *h0_lo, *w0_hi, *w0_lo, *w1_hi, *w1_lo;
    cudaGetSymbolAddress((void**)&xs_hi, g_xs_hi);
    cudaGetSymbolAddress((void**)&xs_lo, g_xs_lo);
    cudaGetSymbolAddress((void**)&h0_hi, g_h0_hi);
    cudaGetSymbolAddress((void**)&h0_lo, g_h0_lo);
    cudaGetSymbolAddress((void**)&w0_hi, g_w0_hi);
    cudaGetSymbolAddress((void**)&w0_lo, g_w0_lo);
    cudaGetSymbolAddress((void**)&w1_hi, g_w1_hi);
    cudaGetSymbolAddress((void**)&w1_lo, g_w1_lo);
    float* h0out;
    cudaGetSymbolAddress((void**)&h0out, g_h0out);

    dim3 gemm_grid(Gc / 128, M_TOK / 128, 2);   // (12, 256, 2)
    dim3 persist_grid(32, 2, 2);                // 128 blocks

    size_t n_w0 = (size_t)2 * Gc * Ec;
    size_t n_w1 = (size_t)2 * Gc * 2 * Hc;
    size_t n_xs = (size_t)M_TOK * Ec;
    size_t n_h0 = (size_t)M_TOK * 2 * Hc;

    split_bf16_kernel<<<(unsigned)((n_w0 + 255) / 256), 256>>>(w_ih0, w0_hi, w0_lo, n_w0);
    split_bf16_kernel<<<(unsigned)((n_w1 + 255) / 256), 256>>>(w_ih1, w1_hi, w1_lo, n_w1);
    split_bf16_kernel<<<(unsigned)((n_xs + 255) / 256), 256>>>(xs, xs_hi, xs_lo, n_xs);

    // ---- layer 0 ----
    gemm_mma<<<gemm_grid, 256>>>(xs_hi, xs_lo, w0_hi, w0_lo, b_ih0, Ec);
    zero_h_kernel<<<(2 * Bc * Hc) / 256, 256>>>();
    gru_persist_mma<<<persist_grid, 128, PERSIST_SMEM>>>(w_hh0, b_hh0, out, 0);
    hy_copy_kernel<<<(2 * Bc * Hc) / 256, 256>>>(out, 0);

    // ---- layer 1 ----
    split_bf16_kernel<<<(unsigned)((n_h0 + 255) / 256), 256>>>(h0out, h0_hi, h0_lo, n_h0);
    gemm_mma<<<gemm_grid, 256>>>(h0_hi, h0_lo, w1_hi, w1_lo, b_ih1, 2 * Hc);
    zero_h_kernel<<<(2 * Bc * Hc) / 256, 256>>>();
    gru_persist_mma<<<persist_grid, 128, PERSIST_SMEM>>>(w_hh1, b_hh1, out, 1);
    hy_copy_kernel<<<(2 * Bc * Hc) / 256, 256>>>(out, 1);
}

// round 9
// speedup vs baseline: 3.1327x; 1.0560x over previous
#include <cuda_runtime.h>
#include <cuda_bf16.h>
#include <cstdint>
#include <math.h>

#define Bc 64
#define Tc 512
#define Ec 512
#define Hc 512
#define Gc 1536            // 3*H
#define M_TOK (Bc*Tc)      // 32768 tokens
#define HY_OFF ((size_t)Bc*Tc*2*Hc)
#define NHALF 16           // blocks per sub-barrier half

// ---------------- device scratch ----------------
// gx layout: [dir][t][bhalf][jc(32)][g(3)][b_local(32)][jl(16)]
__device__ float g_gx[(size_t)2*M_TOK*Gc];
__device__ float g_h0out[(size_t)M_TOK*2*Hc];    // layer0 output [b][t][2H]

// h state as bf16 hi/lo split, layout [buf][dir][batch b][hidden j]
__device__ __nv_bfloat16 g_hAhi[2][2*Bc*Hc];
__device__ __nv_bfloat16 g_hAlo[2][2*Bc*Hc];

// bf16 split operands for gx GEMMs
__device__ __nv_bfloat16 g_xs_hi[(size_t)M_TOK*Ec],  g_xs_lo[(size_t)M_TOK*Ec];
__device__ __nv_bfloat16 g_h0_hi[(size_t)M_TOK*2*Hc], g_h0_lo[(size_t)M_TOK*2*Hc];
__device__ __nv_bfloat16 g_w0_hi[(size_t)2*Gc*Ec],   g_w0_lo[(size_t)2*Gc*Ec];
__device__ __nv_bfloat16 g_w1_hi[(size_t)2*Gc*2*Hc], g_w1_lo[(size_t)2*Gc*2*Hc];

// sub-barrier state: [group(4)][half(2)], padded lines
__device__ int g_bar_cnt[4 * 2 * 32];
__device__ volatile int g_bar_gen2[4 * 2 * 32];

// warp-mma helpers (base PTX, no 'a'-features)
#define LDSM4(r0, r1, r2, r3, addr) \
    asm volatile("ldmatrix.sync.aligned.m8n8.x4.shared.b16 {%0,%1,%2,%3}, [%4];" \
                 : "=r"(r0), "=r"(r1), "=r"(r2), "=r"(r3) : "r"(addr))

#define LDSM2(r0, r1, addr) \
    asm volatile("ldmatrix.sync.aligned.m8n8.x2.shared.b16 {%0,%1}, [%2];" \
                 : "=r"(r0), "=r"(r1) : "r"(addr))

#define MMA16816(d, a, b0, b1) \
    asm volatile("mma.sync.aligned.m16n8k16.row.col.f32.bf16.bf16.f32 " \
                 "{%0,%1,%2,%3}, {%4,%5,%6,%7}, {%8,%9}, {%0,%1,%2,%3};" \
                 : "+f"(d[0]), "+f"(d[1]), "+f"(d[2]), "+f"(d[3]) \
                 : "r"(a[0]), "r"(a[1]), "r"(a[2]), "r"(a[3]), "r"(b0), "r"(b1))

#define CP_ASYNC16(saddr, gptr) \
    asm volatile("cp.async.cg.shared.global [%0], [%1], 16;" \
                 :: "r"(saddr), "l"(gptr) : "memory")
#define CP_COMMIT() asm volatile("cp.async.commit_group;" ::: "memory")
#define CP_WAIT1()  asm volatile("cp.async.wait_group 1;" ::: "memory")
#define CP_WAIT0()  asm volatile("cp.async.wait_group 0;" ::: "memory")

__device__ __forceinline__ uint32_t smem_u32(const void* p) {
    uint32_t a;
    asm("{ .reg .u64 t; cvta.to.shared.u64 t, %1; cvt.u32.u64 %0, t; }" : "=r"(a) : "l"(p));
    return a;
}

// ---------------- bf16 split prep ----------------
__global__ void split_bf16_kernel(const float* __restrict__ src,
                                  __nv_bfloat16* __restrict__ hi,
                                  __nv_bfloat16* __restrict__ lo, size_t n) {
    size_t i = (size_t)blockIdx.x * blockDim.x + threadIdx.x;
    if (i >= n) return;
    float a = src[i];
    __nv_bfloat16 h = __float2bfloat16(a);
    hi[i] = h;
    lo[i] = __float2bfloat16(a - __bfloat162float(h));
}

// ---------------- zero hidden state (buf 0, both splits) ----------------
__global__ void zero_h_kernel() {
    int i = blockIdx.x * blockDim.x + threadIdx.x;   // 2*B*H = 65536
    g_hAhi[0][i] = __float2bfloat16(0.0f);
    g_hAlo[0][i] = __float2bfloat16(0.0f);
}

// ---------------- tensor-core gx GEMM (unchanged, proven R4-R8) ------------
#define KC 32
#define PITCH 40

__global__ void __launch_bounds__(256, 2)
gemm_mma(const __nv_bfloat16* __restrict__ Ahi, const __nv_bfloat16* __restrict__ Alo,
         const __nv_bfloat16* __restrict__ Whi, const __nv_bfloat16* __restrict__ Wlo,
         const float* __restrict__ bias, int K)
{
    __shared__ __nv_bfloat16 sAhi[128 * PITCH], sAlo[128 * PITCH];
    __shared__ __nv_bfloat16 sBhi[128 * PITCH], sBlo[128 * PITCH];

    int tid  = threadIdx.x;
    int wid  = tid >> 5, lane = tid & 31;
    int dir  = blockIdx.z;
    int n0   = blockIdx.x * 128;
    int m0   = blockIdx.y * 128;
    int wm   = wid >> 1;
    int wn   = wid & 1;

    const __nv_bfloat16* bhi = Whi + (size_t)dir * Gc * K;
    const __nv_bfloat16* blo = Wlo + (size_t)dir * Gc * K;
    float* C = g_gx + (size_t)dir * M_TOK * Gc;
    const float* bp = bias + dir * Gc;

    float acc[2][8][4];
#pragma unroll
    for (int i = 0; i < 2; i++)
#pragma unroll
        for (int j = 0; j < 8; j++)
#pragma unroll
            for (int q = 0; q < 4; q++) acc[i][j][q] = 0.0f;

    uint32_t uAhi = smem_u32(sAhi), uAlo = smem_u32(sAlo);
    uint32_t uBhi = smem_u32(sBhi), uBlo = smem_u32(sBlo);

    int a_row = (lane & 15);
    int a_col = (lane >> 4) * 8;
    int b_row = (lane & 7) + ((lane >> 4) & 1) * 8;
    int b_col = ((lane >> 3) & 1) * 8;

    const int nchunks = K / KC;
    for (int c = 0; c < nchunks; c++) {
        int k0 = c * KC;
        __syncthreads();
#pragma unroll
        for (int p = 0; p < 2; p++) {
            int idx = p * 256 + tid;
            int r   = idx >> 2;
            int c4  = idx & 3;
            size_t ga = (size_t)(m0 + r) * K + k0 + c4 * 8;
            size_t gb = (size_t)(n0 + r) * K + k0 + c4 * 8;
            int so = r * PITCH + c4 * 8;
            *(uint4*)&sAhi[so] = *(const uint4*)(Ahi + ga);
            *(uint4*)&sAlo[so] = *(const uint4*)(Alo + ga);
            *(uint4*)&sBhi[so] = *(const uint4*)(bhi + gb);
            *(uint4*)&sBlo[so] = *(const uint4*)(blo + gb);
        }
        __syncthreads();

#pragma unroll
        for (int kk = 0; kk < 2; kk++) {
            int k16 = kk * 16;
            uint32_t ahi[2][4], alo[2][4];
#pragma unroll
            for (int mt = 0; mt < 2; mt++) {
                uint32_t off = 2u * ((wm * 32 + mt * 16 + a_row) * PITCH + k16 + a_col);
                LDSM4(ahi[mt][0], ahi[mt][1], ahi[mt][2], ahi[mt][3], uAhi + off);
                LDSM4(alo[mt][0], alo[mt][1], alo[mt][2], alo[mt][3], uAlo + off);
            }
#pragma unroll
            for (int np = 0; np < 4; np++) {
                uint32_t off = 2u * ((wn * 64 + np * 16 + b_row) * PITCH + k16 + b_col);
                uint32_t bh0, bh1, bh2, bh3, bl0, bl1, bl2, bl3;
                LDSM4(bh0, bh1, bh2, bh3, uBhi + off);
                LDSM4(bl0, bl1, bl2, bl3, uBlo + off);
#pragma unroll
                for (int mt = 0; mt < 2; mt++) {
                    MMA16816(acc[mt][np * 2 + 0], ahi[mt], bh0, bh1);
                    MMA16816(acc[mt][np * 2 + 0], ahi[mt], bl0, bl1);
                    MMA16816(acc[mt][np * 2 + 0], alo[mt], bh0, bh1);
                    MMA16816(acc[mt][np * 2 + 1], ahi[mt], bh2, bh3);
                    MMA16816(acc[mt][np * 2 + 1], ahi[mt], bl2, bl3);
                    MMA16816(acc[mt][np * 2 + 1], alo[mt], bh2, bh3);
                }
            }
        }
    }

    // epilogue: write recurrence-friendly gx layout
#pragma unroll
    for (int mt = 0; mt < 2; mt++) {
#pragma unroll
        for (int nt = 0; nt < 8; nt++) {
            int row = m0 + wm * 32 + mt * 16 + (lane >> 2);
            int col = n0 + wn * 64 + nt * 8 + (lane & 3) * 2;
            float b0 = bp[col], b1 = bp[col + 1];
            int g = col >> 9, j = col & 511;
            int jc = j >> 4, jl = j & 15;
#pragma unroll
            for (int half = 0; half < 2; half++) {
                int r = row + half * 8;
                int bb = r >> 9, tt = r & 511;
                size_t addr = (size_t)tt * 98304 + (size_t)(bb >> 5) * 49152
                            + jc * 1536 + g * 512 + (bb & 31) * 16 + jl;
                float2 v = half ? make_float2(acc[mt][nt][2] + b0, acc[mt][nt][3] + b1)
                                : make_float2(acc[mt][nt][0] + b0, acc[mt][nt][1] + b1);
                *(float2*)&C[addr] = v;
            }
        }
    }
}

// ---------------- persistent MMA recurrence (256 thr, split-k barriers) ----
#define RPITCH 520
#define PG 41
#define OFF_WHI 0
#define SZ_W    (48 * RPITCH * 2)
#define OFF_WLO (OFF_WHI + SZ_W)
#define OFF_HHI (OFF_WLO + SZ_W)
#define SZ_H    (32 * RPITCH * 2)
#define OFF_HLO (OFF_HHI + SZ_H)
#define OFF_G   (OFF_HLO + SZ_H)             // [48][41] floats = 7872B
#define OFF_GX  (OFF_G + 48 * PG * 4)        // [2][3][32][16] floats = 12288B
#define OFF_X   (OFF_GX + 12288)             // [32][16] floats = 2048B
#define PERSIST_SMEM (OFF_X + 2048)          // 188608 bytes

__global__ void __launch_bounds__(256, 1)
gru_persist_mma(const float* __restrict__ w_hh,
                const float* __restrict__ b_hh,
                float* __restrict__ out_l1,
                int layer)
{
    extern __shared__ char sm[];
    __nv_bfloat16* sWhi = (__nv_bfloat16*)(sm + OFF_WHI);
    __nv_bfloat16* sWlo = (__nv_bfloat16*)(sm + OFF_WLO);
    __nv_bfloat16* sHhi = (__nv_bfloat16*)(sm + OFF_HHI);
    __nv_bfloat16* sHlo = (__nv_bfloat16*)(sm + OFF_HLO);
    float* sG  = (float*)(sm + OFF_G);    // [48 gate rows][41]
    float* sGX = (float*)(sm + OFF_GX);   // [2][1536]
    float* sX  = (float*)(sm + OFF_X);    // [32][16] h_new exchange

    int tid = threadIdx.x, lane = tid & 31, wid = tid >> 5;
    int dir   = blockIdx.z;
    int bhalf = blockIdx.y;
    int j0    = blockIdx.x * 16;
    int b0    = bhalf * 32;
    int grp   = dir * 2 + bhalf;
    int myhalf = blockIdx.x >> 4;          // jc<16 -> half 0 (cols<256)
    int ilo = (grp * 2 + 0) * 32;
    int ihi = (grp * 2 + 1) * 32;
    int imine = (grp * 2 + myhalf) * 32;

    // replay-safe generation bases (read before any arrive in this launch)
    int gbase_lo = g_bar_gen2[ilo];
    int gbase_hi = g_bar_gen2[ihi];
    int gbase_mine = myhalf ? gbase_hi : gbase_lo;

    int wm = wid & 1;            // MMA warps 0..3: M-tile
    int wn2 = wid >> 1;          // N-half (only meaningful for wid<4)
    int nbase = wn2 * 24;
    int m_base = wm * 16;

    int jl = tid & 15;           // unit
    int lbase = tid >> 4;        // 0..15 -> batches lbase, lbase+16
    int jglob = j0 + jl;

    int lb2 = tid >> 3;          // writer batch 0..31
    int jp  = (tid & 7) * 2;     // writer j-pair

    // one-time: load + split W slice (48 rows, gate-major r = g*16 + jj)
    const float* W = w_hh + (size_t)dir * Gc * Hc;
    for (int idx = tid; idx < 48 * 512; idx += 256) {
        int r = idx >> 9, k = idx & 511;
        int gg = r >> 4, jj = r & 15;
        float w = W[(size_t)(gg * Hc + j0 + jj) * Hc + k];
        __nv_bfloat16 h = __float2bfloat16(w);
        sWhi[r * RPITCH + k] = h;
        sWlo[r * RPITCH + k] = __float2bfloat16(w - __bfloat162float(h));
    }
    float br = __ldg(&b_hh[dir * Gc + jglob]);
    float bz = __ldg(&b_hh[dir * Gc + Hc + jglob]);
    float bn = __ldg(&b_hh[dir * Gc + 2 * Hc + jglob]);

    const float* gxblk = g_gx + (size_t)dir * M_TOK * Gc
                       + (size_t)bhalf * 49152 + (size_t)blockIdx.x * 1536;
    float* hs = (layer == 0) ? g_h0out : out_l1;

    uint32_t uWhi = smem_u32(sWhi), uWlo = smem_u32(sWlo);
    uint32_t uHhi = smem_u32(sHhi), uHlo = smem_u32(sHlo);
    uint32_t uGX  = smem_u32(sGX);

    int a_row = lane & 15, a_col = (lane >> 4) * 8;
    int b_row = (lane & 7) + ((lane >> 4) & 1) * 8, b_col = ((lane >> 3) & 1) * 8;
    int b_row2 = 16 + (lane & 7);

    // prologue: stage gx(0) into sGX buf 0
    {
        int t0 = dir ? (Tc - 1) : 0;
        const float* gxt = gxblk + (size_t)t0 * 98304;
#pragma unroll
        for (int p = 0; p < 2; p++) {
            int idx = tid + p * 256;
            if (idx < 384) CP_ASYNC16(uGX + idx * 16, (const void*)(gxt + idx * 4));
        }
        CP_COMMIT();
    }
    __syncthreads();

    for (int s = 0; s < Tc; s++) {
        int rbuf = s & 1;
        int t = dir ? (Tc - 1 - s) : s;
        const __nv_bfloat16* hAhi = g_hAhi[rbuf] + dir * Bc * Hc;
        const __nv_bfloat16* hAlo = g_hAlo[rbuf] + dir * Bc * Hc;
        __nv_bfloat16* wAhi = g_hAhi[rbuf ^ 1] + dir * Bc * Hc;
        __nv_bfloat16* wAlo = g_hAlo[rbuf ^ 1] + dir * Bc * Hc;

        // ---- poll lo half (h cols [0,256) ready), stage chunk 0 ----
        if (s > 0 && tid == 0) {
            while (g_bar_gen2[ilo] - gbase_lo < s) { }
        }
        __syncthreads();
#pragma unroll
        for (int p = 0; p < 8; p++) {
            int idx = tid + p * 256;            // 0..2047
            int split = idx >> 10;
            int rrow  = (idx >> 5) & 31;
            int c16   = idx & 31;
            const __nv_bfloat16* gsrc =
                (split ? hAlo : hAhi) + (size_t)(b0 + rrow) * Hc + c16 * 8;
            uint32_t sdst = (split ? uHlo : uHhi) + (rrow * RPITCH + c16 * 8) * 2;
            CP_ASYNC16(sdst, (const void*)gsrc);
        }
        CP_COMMIT();

        // ---- poll hi half (overlaps chunk-0 delivery), stage chunk 1 ----
        if (s > 0 && tid == 0) {
            while (g_bar_gen2[ihi] - gbase_hi < s) { }
        }
        __syncthreads();
#pragma unroll
        for (int p = 0; p < 8; p++) {
            int idx = tid + p * 256;
            int split = idx >> 10;
            int rrow  = (idx >> 5) & 31;
            int c16   = idx & 31;
            const __nv_bfloat16* gsrc =
                (split ? hAlo : hAhi) + (size_t)(b0 + rrow) * Hc + 256 + c16 * 8;
            uint32_t sdst = (split ? uHlo : uHhi) + (rrow * RPITCH + 256 + c16 * 8) * 2;
            CP_ASYNC16(sdst, (const void*)gsrc);
        }
        CP_COMMIT();

        float acc[3][4];
#pragma unroll
        for (int i = 0; i < 3; i++)
#pragma unroll
            for (int q = 0; q < 4; q++) acc[i][q] = 0.0f;

        // chunk 0 MMA (gx + chunk0 complete; chunk1 in flight)
        CP_WAIT1();
        __syncthreads();
        if (wid < 4) {
#pragma unroll
            for (int kk = 0; kk < 16; kk++) {
                int k16 = kk;
                uint32_t offA = (uint32_t)(((m_base + a_row) * RPITCH + k16 * 16 + a_col) * 2);
                uint32_t ahi[4], alo[4];
                LDSM4(ahi[0], ahi[1], ahi[2], ahi[3], uHhi + offA);
                LDSM4(alo[0], alo[1], alo[2], alo[3], uHlo + offA);

                uint32_t offB = (uint32_t)(((nbase + b_row) * RPITCH + k16 * 16 + b_col) * 2);
                uint32_t bh0, bh1, bh2, bh3, bl0, bl1, bl2, bl3;
                LDSM4(bh0, bh1, bh2, bh3, uWhi + offB);
                LDSM4(bl0, bl1, bl2, bl3, uWlo + offB);
                MMA16816(acc[0], ahi, bh0, bh1);
                MMA16816(acc[0], ahi, bl0, bl1);
                MMA16816(acc[0], alo, bh0, bh1);
                MMA16816(acc[1], ahi, bh2, bh3);
                MMA16816(acc[1], ahi, bl2, bl3);
                MMA16816(acc[1], alo, bh2, bh3);

                uint32_t offB2 = (uint32_t)(((nbase + b_row2) * RPITCH + k16 * 16 + b_col) * 2);
                uint32_t ch0, ch1, cl0, cl1;
                LDSM2(ch0, ch1, uWhi + offB2);
                LDSM2(cl0, cl1, uWlo + offB2);
                MMA16816(acc[2], ahi, ch0, ch1);
                MMA16816(acc[2], ahi, cl0, cl1);
                MMA16816(acc[2], alo, ch0, ch1);
            }
        }

        // chunk 1 MMA
        CP_WAIT0();
        __syncthreads();
        if (wid < 4) {
#pragma unroll
            for (int kk = 0; kk < 16; kk++) {
                int k16 = 16 + kk;
                uint32_t offA = (uint32_t)(((m_base + a_row) * RPITCH + k16 * 16 + a_col) * 2);
                uint32_t ahi[4], alo[4];
                LDSM4(ahi[0], ahi[1], ahi[2], ahi[3], uHhi + offA);
                LDSM4(alo[0], alo[1], alo[2], alo[3], uHlo + offA);

                uint32_t offB = (uint32_t)(((nbase + b_row) * RPITCH + k16 * 16 + b_col) * 2);
                uint32_t bh0, bh1, bh2, bh3, bl0, bl1, bl2, bl3;
                LDSM4(bh0, bh1, bh2, bh3, uWhi + offB);
                LDSM4(bl0, bl1, bl2, bl3, uWlo + offB);
                MMA16816(acc[0], ahi, bh0, bh1);
                MMA16816(acc[0], ahi, bl0, bl1);
                MMA16816(acc[0], alo, bh0, bh1);
                MMA16816(acc[1], ahi, bh2, bh3);
                MMA16816(acc[1], ahi, bl2, bl3);
                MMA16816(acc[1], alo, bh2, bh3);

                uint32_t offB2 = (uint32_t)(((nbase + b_row2) * RPITCH + k16 * 16 + b_col) * 2);
                uint32_t ch0, ch1, cl0, cl1;
                LDSM2(ch0, ch1, uWhi + offB2);
                LDSM2(cl0, cl1, uWlo + offB2);
                MMA16816(acc[2], ahi, ch0, ch1);
                MMA16816(acc[2], ahi, cl0, cl1);
                MMA16816(acc[2], alo, ch0, ch1);
            }
            // dump gh to sG[gate row][batch row]
#pragma unroll
            for (int nt = 0; nt < 3; nt++) {
                int c0 = nbase + nt * 8 + (lane & 3) * 2;
                int r0 = m_base + (lane >> 2);
                sG[c0 * PG + r0]           = acc[nt][0];
                sG[(c0 + 1) * PG + r0]     = acc[nt][1];
                sG[c0 * PG + r0 + 8]       = acc[nt][2];
                sG[(c0 + 1) * PG + r0 + 8] = acc[nt][3];
            }
        }
        __syncthreads();

        // gate math: thread -> unit jglob, batches lbase and lbase+16
        const float* gxs = sGX + rbuf * 1536;
#pragma unroll
        for (int rep = 0; rep < 2; rep++) {
            int lb = lbase + rep * 16;
            float ghr = sG[jl * PG + lb];
            float ghz = sG[(16 + jl) * PG + lb];
            float ghn = sG[(32 + jl) * PG + lb];
            float gr = gxs[lb * 16 + jl];
            float gz = gxs[512 + lb * 16 + jl];
            float gn = gxs[1024 + lb * 16 + jl];
            float hp = __bfloat162float(sHhi[lb * RPITCH + jglob])
                     + __bfloat162float(sHlo[lb * RPITCH + jglob]);
            float rr = 1.0f / (1.0f + __expf(-(gr + ghr + br)));
            float zz = 1.0f / (1.0f + __expf(-(gz + ghz + bz)));
            float xa = gn + rr * (ghn + bn);
            float e2 = __expf(2.0f * xa);
            float nn = 1.0f - __fdividef(2.0f, e2 + 1.0f);
            sX[lb * 16 + jl] = (1.0f - zz) * nn + zz * hp;
        }
        __syncthreads();

        // h_new global write: one bf16x2 per array per thread
        {
            float v0 = sX[lb2 * 16 + jp];
            float v1 = sX[lb2 * 16 + jp + 1];
            __nv_bfloat16 h0 = __float2bfloat16(v0), h1 = __float2bfloat16(v1);
            __nv_bfloat162 hi01 = {h0, h1};
            __nv_bfloat162 lo01 = {__float2bfloat16(v0 - __bfloat162float(h0)),
                                   __float2bfloat16(v1 - __bfloat162float(h1))};
            size_t base = (size_t)(b0 + lb2) * Hc + j0 + jp;
            *(__nv_bfloat162*)(wAhi + base) = hi01;
            *(__nv_bfloat162*)(wAlo + base) = lo01;
        }
        __syncthreads();

        // arrive at own sub-barrier (skip on last step)
        if (s != Tc - 1 && tid == 0) {
            __threadfence();
            int old = atomicAdd(&g_bar_cnt[imine], 1);
            if (old == NHALF - 1) {
                g_bar_cnt[imine] = 0;
                __threadfence();
                g_bar_gen2[imine] = gbase_mine + s + 1;
            }
        }

        // off-critical-path: hs output + gx prefetch for s+1
        {
            float2 xv = make_float2(sX[lb2 * 16 + jp], sX[lb2 * 16 + jp + 1]);
            *(float2*)&hs[((size_t)(b0 + lb2) * Tc + t) * (2 * Hc) + dir * Hc + j0 + jp] = xv;
        }
        if (s != Tc - 1) {
            int tn = dir ? (Tc - 2 - s) : (s + 1);
            const float* gxt = gxblk + (size_t)tn * 98304;
            uint32_t dstb = uGX + ((s + 1) & 1) * 6144;
#pragma unroll
            for (int p = 0; p < 2; p++) {
                int idx = tid + p * 256;
                if (idx < 384) CP_ASYNC16(dstb + idx * 16, (const void*)(gxt + idx * 4));
            }
            CP_COMMIT();
        }
    }
}

// ---------------- copy final hidden states ----------------
__global__ void hy_copy_kernel(float* __restrict__ d_out, int layer) {
    int i = blockIdx.x * blockDim.x + threadIdx.x;   // 0..65535
    int dir = i >> 15;
    int rem = i & 32767;                              // = b*512 + j
    d_out[HY_OFF + (size_t)(2 * layer + dir) * Bc * Hc + rem] =
        __bfloat162float(g_hAhi[0][dir * Bc * Hc + rem]) +
        __bfloat162float(g_hAlo[0][dir * Bc * Hc + rem]);
}

// ---------------- launch ----------------
extern "C" void kernel_launch(void* const* d_in, const int* in_sizes, int n_in,
                              void* d_out, int out_size)
{
    const float* xs    = (const float*)d_in[0];
    const float* w_ih0 = (const float*)d_in[1];
    const float* w_hh0 = (const float*)d_in[2];
    const float* b_ih0 = (const float*)d_in[3];
    const float* b_hh0 = (const float*)d_in[4];
    const float* w_ih1 = (const float*)d_in[5];
    const float* w_hh1 = (const float*)d_in[6];
    const float* b_ih1 = (const float*)d_in[7];
    const float* b_hh1 = (const float*)d_in[8];
    float* out = (float*)d_out;

    cudaFuncSetAttribute(gru_persist_mma,
                         cudaFuncAttributeMaxDynamicSharedMemorySize, PERSIST_SMEM);

    __nv_bfloat16 *xs_hi, *xs_lo, *h0_hi, *h0_lo, *w0_hi, *w0_lo, *w1_hi, *w1_lo;
    cudaGetSymbolAddress((void**)&xs_hi, g_xs_hi);
    cudaGetSymbolAddress((void**)&xs_lo, g_xs_lo);
    cudaGetSymbolAddress((void**)&h0_hi, g_h0_hi);
    cudaGetSymbolAddress((void**)&h0_lo, g_h0_lo);
    cudaGetSymbolAddress((void**)&w0_hi, g_w0_hi);
    cudaGetSymbolAddress((void**)&w0_lo, g_w0_lo);
    cudaGetSymbolAddress((void**)&w1_hi, g_w1_hi);
    cudaGetSymbolAddress((void**)&w1_lo, g_w1_lo);
    float* h0out;
    cudaGetSymbolAddress((void**)&h0out, g_h0out);

    dim3 gemm_grid(Gc / 128, M_TOK / 128, 2);   // (12, 256, 2)
    dim3 persist_grid(32, 2, 2);                // 128 blocks

    size_t n_w0 = (size_t)2 * Gc * Ec;
    size_t n_w1 = (size_t)2 * Gc * 2 * Hc;
    size_t n_xs = (size_t)M_TOK * Ec;
    size_t n_h0 = (size_t)M_TOK * 2 * Hc;

    split_bf16_kernel<<<(unsigned)((n_w0 + 255) / 256), 256>>>(w_ih0, w0_hi, w0_lo, n_w0);
    split_bf16_kernel<<<(unsigned)((n_w1 + 255) / 256), 256>>>(w_ih1, w1_hi, w1_lo, n_w1);
    split_bf16_kernel<<<(unsigned)((n_xs + 255) / 256), 256>>>(xs, xs_hi, xs_lo, n_xs);

    // ---- layer 0 ----
    gemm_mma<<<gemm_grid, 256>>>(xs_hi, xs_lo, w0_hi, w0_lo, b_ih0, Ec);
    zero_h_kernel<<<(2 * Bc * Hc) / 256, 256>>>();
    gru_persist_mma<<<persist_grid, 256, PERSIST_SMEM>>>(w_hh0, b_hh0, out, 0);
    hy_copy_kernel<<<(2 * Bc * Hc) / 256, 256>>>(out, 0);

    // ---- layer 1 ----
    split_bf16_kernel<<<(unsigned)((n_h0 + 255) / 256), 256>>>(h0out, h0_hi, h0_lo, n_h0);
    gemm_mma<<<gemm_grid, 256>>>(h0_hi, h0_lo, w1_hi, w1_lo, b_ih1, 2 * Hc);
    zero_h_kernel<<<(2 * Bc * Hc) / 256, 256>>>();
    gru_persist_mma<<<persist_grid, 256, PERSIST_SMEM>>>(w_hh1, b_hh1, out, 1);
    hy_copy_kernel<<<(2 * Bc * Hc) / 256, 256>>>(out, 1);
}

// round 10
// speedup vs baseline: 3.3468x; 1.0684x over previous
#include <cuda_runtime.h>
#include <cuda_bf16.h>
#include <cstdint>
#include <math.h>

#define Bc 64
#define Tc 512
#define Ec 512
#define Hc 512
#define Gc 1536            // 3*H
#define M_TOK (Bc*Tc)      // 32768 tokens
#define HY_OFF ((size_t)Bc*Tc*2*Hc)
#define NHALF 16           // blocks per sub-barrier half

// ---------------- device scratch ----------------
// gx layout: [dir][t][bhalf][jc(32)][g(3)][b_local(32)][jl(16)]
__device__ float g_gx[(size_t)2*M_TOK*Gc];
__device__ float g_h0out[(size_t)M_TOK*2*Hc];    // layer0 output [b][t][2H]

// h state bf16 hi/lo, layout [buf][(dir*2+jhalf)*64 + b][256] with XOR-16B swizzle
__device__ __nv_bfloat16 g_hAhi[2][2*2*64*256];
__device__ __nv_bfloat16 g_hAlo[2][2*2*64*256];

// bf16 split operands for gx GEMMs
__device__ __nv_bfloat16 g_xs_hi[(size_t)M_TOK*Ec],  g_xs_lo[(size_t)M_TOK*Ec];
__device__ __nv_bfloat16 g_h0_hi[(size_t)M_TOK*2*Hc], g_h0_lo[(size_t)M_TOK*2*Hc];
__device__ __nv_bfloat16 g_w0_hi[(size_t)2*Gc*Ec],   g_w0_lo[(size_t)2*Gc*Ec];
__device__ __nv_bfloat16 g_w1_hi[(size_t)2*Gc*2*Hc], g_w1_lo[(size_t)2*Gc*2*Hc];

// sub-barrier state: [group(4)][half(2)], padded lines
__device__ int g_bar_cnt[4 * 2 * 32];
__device__ volatile int g_bar_gen2[4 * 2 * 32];

// warp-mma helpers (base PTX)
#define LDSM4(r0, r1, r2, r3, addr) \
    asm volatile("ldmatrix.sync.aligned.m8n8.x4.shared.b16 {%0,%1,%2,%3}, [%4];" \
                 : "=r"(r0), "=r"(r1), "=r"(r2), "=r"(r3) : "r"(addr))

#define LDSM2(r0, r1, addr) \
    asm volatile("ldmatrix.sync.aligned.m8n8.x2.shared.b16 {%0,%1}, [%2];" \
                 : "=r"(r0), "=r"(r1) : "r"(addr))

#define MMA16816(d, a, b0, b1) \
    asm volatile("mma.sync.aligned.m16n8k16.row.col.f32.bf16.bf16.f32 " \
                 "{%0,%1,%2,%3}, {%4,%5,%6,%7}, {%8,%9}, {%0,%1,%2,%3};" \
                 : "+f"(d[0]), "+f"(d[1]), "+f"(d[2]), "+f"(d[3]) \
                 : "r"(a[0]), "r"(a[1]), "r"(a[2]), "r"(a[3]), "r"(b0), "r"(b1))

// bulk async copy (sm_90 base) + mbarrier
#define BULK_G2S(dst, src, bytes, mbar) \
    asm volatile("cp.async.bulk.shared::cluster.global.mbarrier::complete_tx::bytes " \
                 "[%0], [%1], %2, [%3];" \
                 :: "r"(dst), "l"(src), "r"(bytes), "r"(mbar) : "memory")
#define MBAR_INIT(mbar, cnt) \
    asm volatile("mbarrier.init.shared.b64 [%0], %1;" :: "r"(mbar), "r"(cnt) : "memory")
#define MBAR_INVAL(mbar) \
    asm volatile("mbarrier.inval.shared.b64 [%0];" :: "r"(mbar) : "memory")
#define MBAR_EXPECT(mbar, bytes) \
    asm volatile("mbarrier.arrive.expect_tx.shared.b64 _, [%0], %1;" \
                 :: "r"(mbar), "r"(bytes) : "memory")
#define MBAR_WAIT(mbar, par) do { \
    asm volatile("{\n\t.reg .pred P;\n\tW%=:\n\t" \
        "mbarrier.try_wait.parity.acquire.cta.shared::cta.b64 P, [%0], %1, 0x989680;\n\t" \
        "@!P bra W%=;\n\t}" :: "r"(mbar), "r"(par) : "memory"); \
} while (0)

__device__ __forceinline__ uint32_t smem_u32(const void* p) {
    uint32_t a;
    asm("{ .reg .u64 t; cvta.to.shared.u64 t, %1; cvt.u32.u64 %0, t; }" : "=r"(a) : "l"(p));
    return a;
}

// ---------------- bf16 split prep ----------------
__global__ void split_bf16_kernel(const float* __restrict__ src,
                                  __nv_bfloat16* __restrict__ hi,
                                  __nv_bfloat16* __restrict__ lo, size_t n) {
    size_t i = (size_t)blockIdx.x * blockDim.x + threadIdx.x;
    if (i >= n) return;
    float a = src[i];
    __nv_bfloat16 h = __float2bfloat16(a);
    hi[i] = h;
    lo[i] = __float2bfloat16(a - __bfloat162float(h));
}

// ---------------- zero hidden state (buf 0, both splits) ----------------
__global__ void zero_h_kernel() {
    int i = blockIdx.x * blockDim.x + threadIdx.x;   // 2*2*64*256 = 65536
    g_hAhi[0][i] = __float2bfloat16(0.0f);
    g_hAlo[0][i] = __float2bfloat16(0.0f);
}

// ---------------- tensor-core gx GEMM (unchanged, proven R4-R9) ------------
#define KC 32
#define PITCH 40

__global__ void __launch_bounds__(256, 2)
gemm_mma(const __nv_bfloat16* __restrict__ Ahi, const __nv_bfloat16* __restrict__ Alo,
         const __nv_bfloat16* __restrict__ Whi, const __nv_bfloat16* __restrict__ Wlo,
         const float* __restrict__ bias, int K)
{
    __shared__ __nv_bfloat16 sAhi[128 * PITCH], sAlo[128 * PITCH];
    __shared__ __nv_bfloat16 sBhi[128 * PITCH], sBlo[128 * PITCH];

    int tid  = threadIdx.x;
    int wid  = tid >> 5, lane = tid & 31;
    int dir  = blockIdx.z;
    int n0   = blockIdx.x * 128;
    int m0   = blockIdx.y * 128;
    int wm   = wid >> 1;
    int wn   = wid & 1;

    const __nv_bfloat16* bhi = Whi + (size_t)dir * Gc * K;
    const __nv_bfloat16* blo = Wlo + (size_t)dir * Gc * K;
    float* C = g_gx + (size_t)dir * M_TOK * Gc;
    const float* bp = bias + dir * Gc;

    float acc[2][8][4];
#pragma unroll
    for (int i = 0; i < 2; i++)
#pragma unroll
        for (int j = 0; j < 8; j++)
#pragma unroll
            for (int q = 0; q < 4; q++) acc[i][j][q] = 0.0f;

    uint32_t uAhi = smem_u32(sAhi), uAlo = smem_u32(sAlo);
    uint32_t uBhi = smem_u32(sBhi), uBlo = smem_u32(sBlo);

    int a_row = (lane & 15);
    int a_col = (lane >> 4) * 8;
    int b_row = (lane & 7) + ((lane >> 4) & 1) * 8;
    int b_col = ((lane >> 3) & 1) * 8;

    const int nchunks = K / KC;
    for (int c = 0; c < nchunks; c++) {
        int k0 = c * KC;
        __syncthreads();
#pragma unroll
        for (int p = 0; p < 2; p++) {
            int idx = p * 256 + tid;
            int r   = idx >> 2;
            int c4  = idx & 3;
            size_t ga = (size_t)(m0 + r) * K + k0 + c4 * 8;
            size_t gb = (size_t)(n0 + r) * K + k0 + c4 * 8;
            int so = r * PITCH + c4 * 8;
            *(uint4*)&sAhi[so] = *(const uint4*)(Ahi + ga);
            *(uint4*)&sAlo[so] = *(const uint4*)(Alo + ga);
            *(uint4*)&sBhi[so] = *(const uint4*)(bhi + gb);
            *(uint4*)&sBlo[so] = *(const uint4*)(blo + gb);
        }
        __syncthreads();

#pragma unroll
        for (int kk = 0; kk < 2; kk++) {
            int k16 = kk * 16;
            uint32_t ahi[2][4], alo[2][4];
#pragma unroll
            for (int mt = 0; mt < 2; mt++) {
                uint32_t off = 2u * ((wm * 32 + mt * 16 + a_row) * PITCH + k16 + a_col);
                LDSM4(ahi[mt][0], ahi[mt][1], ahi[mt][2], ahi[mt][3], uAhi + off);
                LDSM4(alo[mt][0], alo[mt][1], alo[mt][2], alo[mt][3], uAlo + off);
            }
#pragma unroll
            for (int np = 0; np < 4; np++) {
                uint32_t off = 2u * ((wn * 64 + np * 16 + b_row) * PITCH + k16 + b_col);
                uint32_t bh0, bh1, bh2, bh3, bl0, bl1, bl2, bl3;
                LDSM4(bh0, bh1, bh2, bh3, uBhi + off);
                LDSM4(bl0, bl1, bl2, bl3, uBlo + off);
#pragma unroll
                for (int mt = 0; mt < 2; mt++) {
                    MMA16816(acc[mt][np * 2 + 0], ahi[mt], bh0, bh1);
                    MMA16816(acc[mt][np * 2 + 0], ahi[mt], bl0, bl1);
                    MMA16816(acc[mt][np * 2 + 0], alo[mt], bh0, bh1);
                    MMA16816(acc[mt][np * 2 + 1], ahi[mt], bh2, bh3);
                    MMA16816(acc[mt][np * 2 + 1], ahi[mt], bl2, bl3);
                    MMA16816(acc[mt][np * 2 + 1], alo[mt], bh2, bh3);
                }
            }
        }
    }

    // epilogue: write recurrence-friendly gx layout
#pragma unroll
    for (int mt = 0; mt < 2; mt++) {
#pragma unroll
        for (int nt = 0; nt < 8; nt++) {
            int row = m0 + wm * 32 + mt * 16 + (lane >> 2);
            int col = n0 + wn * 64 + nt * 8 + (lane & 3) * 2;
            float b0 = bp[col], b1 = bp[col + 1];
            int g = col >> 9, j = col & 511;
            int jc = j >> 4, jl = j & 15;
#pragma unroll
            for (int half = 0; half < 2; half++) {
                int r = row + half * 8;
                int bb = r >> 9, tt = r & 511;
                size_t addr = (size_t)tt * 98304 + (size_t)(bb >> 5) * 49152
                            + jc * 1536 + g * 512 + (bb & 31) * 16 + jl;
                float2 v = half ? make_float2(acc[mt][nt][2] + b0, acc[mt][nt][3] + b1)
                                : make_float2(acc[mt][nt][0] + b0, acc[mt][nt][1] + b1);
                *(float2*)&C[addr] = v;
            }
        }
    }
}

// ---------------- persistent MMA recurrence (bulk-copy staging) ------------
#define RPITCH 520
#define PG 41
#define OFF_WHI 0
#define SZ_W    (48 * RPITCH * 2)               // 49920
#define OFF_WLO (OFF_WHI + SZ_W)
#define OFF_HHI (OFF_WLO + SZ_W)                // 99840; [kh][32][256] swizzled
#define SZ_H    (2 * 32 * 256 * 2)              // 32768
#define OFF_HLO (OFF_HHI + SZ_H)
#define OFF_G   (OFF_HLO + SZ_H)                // [48][41] floats = 7872B
#define OFF_GX  (OFF_G + 48 * PG * 4)           // [2][1536] floats = 12288B
#define OFF_X   (OFF_GX + 12288)                // [32][16] floats = 2048B
#define OFF_MB  (OFF_X + 2048)                  // 4 mbarriers
#define PERSIST_SMEM (OFF_MB + 64)              // 187712 bytes

__global__ void __launch_bounds__(256, 1)
gru_persist_mma(const float* __restrict__ w_hh,
                const float* __restrict__ b_hh,
                float* __restrict__ out_l1,
                int layer)
{
    extern __shared__ char sm[];
    __nv_bfloat16* sWhi = (__nv_bfloat16*)(sm + OFF_WHI);
    __nv_bfloat16* sWlo = (__nv_bfloat16*)(sm + OFF_WLO);
    __nv_bfloat16* sHhi = (__nv_bfloat16*)(sm + OFF_HHI);
    __nv_bfloat16* sHlo = (__nv_bfloat16*)(sm + OFF_HLO);
    float* sG  = (float*)(sm + OFF_G);
    float* sGX = (float*)(sm + OFF_GX);
    float* sX  = (float*)(sm + OFF_X);

    int tid = threadIdx.x, lane = tid & 31, wid = tid >> 5;
    int dir   = blockIdx.z;
    int bhalf = blockIdx.y;
    int j0    = blockIdx.x * 16;
    int b0    = bhalf * 32;
    int grp   = dir * 2 + bhalf;
    int myhalf = blockIdx.x >> 4;          // j0 < 256 -> half 0
    int ilo = (grp * 2 + 0) * 32;
    int ihi = (grp * 2 + 1) * 32;
    int imine = (grp * 2 + myhalf) * 32;

    int gbase_lo = g_bar_gen2[ilo];
    int gbase_hi = g_bar_gen2[ihi];
    int gbase_mine = myhalf ? gbase_hi : gbase_lo;

    uint32_t sbase = smem_u32(sm);
    uint32_t mb_h0 = sbase + OFF_MB;
    uint32_t mb_h1 = sbase + OFF_MB + 8;
    uint32_t mb_g0 = sbase + OFF_MB + 16;
    uint32_t mb_g1 = sbase + OFF_MB + 24;

    int wm = wid & 1;
    int wn2 = wid >> 1;
    int nbase = wn2 * 24;
    int m_base = wm * 16;

    int jl = tid & 15;
    int lbase = tid >> 4;
    int jglob = j0 + jl;

    int lb2 = tid >> 3;          // writer batch 0..31
    int jp  = (tid & 7) * 2;     // writer j-pair

    // one-time: load + split W slice (48 rows, gate-major r = g*16 + jj)
    const float* W = w_hh + (size_t)dir * Gc * Hc;
    for (int idx = tid; idx < 48 * 512; idx += 256) {
        int r = idx >> 9, k = idx & 511;
        int gg = r >> 4, jj = r & 15;
        float w = W[(size_t)(gg * Hc + j0 + jj) * Hc + k];
        __nv_bfloat16 h = __float2bfloat16(w);
        sWhi[r * RPITCH + k] = h;
        sWlo[r * RPITCH + k] = __float2bfloat16(w - __bfloat162float(h));
    }
    float br = __ldg(&b_hh[dir * Gc + jglob]);
    float bz = __ldg(&b_hh[dir * Gc + Hc + jglob]);
    float bn = __ldg(&b_hh[dir * Gc + 2 * Hc + jglob]);

    const float* gxblk = g_gx + (size_t)dir * M_TOK * Gc
                       + (size_t)bhalf * 49152 + (size_t)blockIdx.x * 1536;
    float* hs = (layer == 0) ? g_h0out : out_l1;

    uint32_t uWhi = smem_u32(sWhi), uWlo = smem_u32(sWlo);
    uint32_t uHhi = smem_u32(sHhi), uHlo = smem_u32(sHlo);
    uint32_t uGX  = smem_u32(sGX);

    int a_row = lane & 15, a_col = (lane >> 4) * 8;
    int b_row = (lane & 7) + ((lane >> 4) & 1) * 8, b_col = ((lane >> 3) & 1) * 8;
    int b_row2 = 16 + (lane & 7);

    // writer constants (swizzled global h layout)
    int wkh   = j0 >> 8;                 // which j-half this block writes
    int wjloc = (j0 & 255) + jp;
    int wunit = (wjloc >> 3) ^ (lb2 & 7);
    int woff  = ((dir * 2 + wkh) * 64 + (b0 + lb2)) * 256 + (wunit << 3) + (wjloc & 7);
    // hp reader constants
    int hkh   = jglob >> 8;
    int hjloc = jglob & 255;

    if (tid == 0) {
        MBAR_INIT(mb_h0, 1); MBAR_INIT(mb_h1, 1);
        MBAR_INIT(mb_g0, 1); MBAR_INIT(mb_g1, 1);
    }
    __syncthreads();

    // prologue: gx(0) bulk into buf 0
    if (tid == 0) {
        int t0 = dir ? (Tc - 1) : 0;
        MBAR_EXPECT(mb_g0, 6144u);
        BULK_G2S(uGX, (const void*)(gxblk + (size_t)t0 * 98304), 6144u, mb_g0);
    }
    int gxph0 = 0, gxph1 = 0;

    for (int s = 0; s < Tc; s++) {
        int rbuf = s & 1;
        int par = s & 1;
        int t = dir ? (Tc - 1 - s) : s;
        const __nv_bfloat16* hAhi = g_hAhi[rbuf];
        const __nv_bfloat16* hAlo = g_hAlo[rbuf];
        __nv_bfloat16* wAhi = g_hAhi[rbuf ^ 1];
        __nv_bfloat16* wAlo = g_hAlo[rbuf ^ 1];

        // tid0: poll lo half ready -> issue k-half-0 bulks; then hi half
        if (tid == 0) {
            if (s > 0) while (g_bar_gen2[ilo] - gbase_lo < s) { }
            size_t src0 = (size_t)((dir * 2 + 0) * 64 + b0) * 256;
            MBAR_EXPECT(mb_h0, 32768u);
            BULK_G2S(uHhi, (const void*)(hAhi + src0), 16384u, mb_h0);
            BULK_G2S(uHlo, (const void*)(hAlo + src0), 16384u, mb_h0);
            if (s > 0) while (g_bar_gen2[ihi] - gbase_hi < s) { }
            size_t src1 = (size_t)((dir * 2 + 1) * 64 + b0) * 256;
            MBAR_EXPECT(mb_h1, 32768u);
            BULK_G2S(uHhi + 16384, (const void*)(hAhi + src1), 16384u, mb_h1);
            BULK_G2S(uHlo + 16384, (const void*)(hAlo + src1), 16384u, mb_h1);
        }

        float acc[3][4];
#pragma unroll
        for (int i = 0; i < 3; i++)
#pragma unroll
            for (int q = 0; q < 4; q++) acc[i][q] = 0.0f;

        // ---- k-half 0 ----
        MBAR_WAIT(mb_h0, par);
        if (wid < 4) {
#pragma unroll
            for (int kk = 0; kk < 16; kk++) {
                int unitA = kk * 2 + (a_col >> 3);
                int rowA = m_base + a_row;
                uint32_t offA = (uint32_t)(rowA * 512 + ((unitA ^ (rowA & 7)) << 4));
                uint32_t ahi[4], alo[4];
                LDSM4(ahi[0], ahi[1], ahi[2], ahi[3], uHhi + offA);
                LDSM4(alo[0], alo[1], alo[2], alo[3], uHlo + offA);

                uint32_t offB = (uint32_t)(((nbase + b_row) * RPITCH + kk * 16 + b_col) * 2);
                uint32_t bh0, bh1, bh2, bh3, bl0, bl1, bl2, bl3;
                LDSM4(bh0, bh1, bh2, bh3, uWhi + offB);
                LDSM4(bl0, bl1, bl2, bl3, uWlo + offB);
                MMA16816(acc[0], ahi, bh0, bh1);
                MMA16816(acc[0], ahi, bl0, bl1);
                MMA16816(acc[0], alo, bh0, bh1);
                MMA16816(acc[1], ahi, bh2, bh3);
                MMA16816(acc[1], ahi, bl2, bl3);
                MMA16816(acc[1], alo, bh2, bh3);

                uint32_t offB2 = (uint32_t)(((nbase + b_row2) * RPITCH + kk * 16 + b_col) * 2);
                uint32_t ch0, ch1, cl0, cl1;
                LDSM2(ch0, ch1, uWhi + offB2);
                LDSM2(cl0, cl1, uWlo + offB2);
                MMA16816(acc[2], ahi, ch0, ch1);
                MMA16816(acc[2], ahi, cl0, cl1);
                MMA16816(acc[2], alo, ch0, ch1);
            }
        }

        // ---- k-half 1 ----
        MBAR_WAIT(mb_h1, par);
        if (wid < 4) {
#pragma unroll
            for (int kk = 0; kk < 16; kk++) {
                int k16 = 16 + kk;
                int unitA = kk * 2 + (a_col >> 3);
                int rowA = m_base + a_row;
                uint32_t offA = (uint32_t)(16384 + rowA * 512 + ((unitA ^ (rowA & 7)) << 4));
                uint32_t ahi[4], alo[4];
                LDSM4(ahi[0], ahi[1], ahi[2], ahi[3], uHhi + offA);
                LDSM4(alo[0], alo[1], alo[2], alo[3], uHlo + offA);

                uint32_t offB = (uint32_t)(((nbase + b_row) * RPITCH + k16 * 16 + b_col) * 2);
                uint32_t bh0, bh1, bh2, bh3, bl0, bl1, bl2, bl3;
                LDSM4(bh0, bh1, bh2, bh3, uWhi + offB);
                LDSM4(bl0, bl1, bl2, bl3, uWlo + offB);
                MMA16816(acc[0], ahi, bh0, bh1);
                MMA16816(acc[0], ahi, bl0, bl1);
                MMA16816(acc[0], alo, bh0, bh1);
                MMA16816(acc[1], ahi, bh2, bh3);
                MMA16816(acc[1], ahi, bl2, bl3);
                MMA16816(acc[1], alo, bh2, bh3);

                uint32_t offB2 = (uint32_t)(((nbase + b_row2) * RPITCH + k16 * 16 + b_col) * 2);
                uint32_t ch0, ch1, cl0, cl1;
                LDSM2(ch0, ch1, uWhi + offB2);
                LDSM2(cl0, cl1, uWlo + offB2);
                MMA16816(acc[2], ahi, ch0, ch1);
                MMA16816(acc[2], ahi, cl0, cl1);
                MMA16816(acc[2], alo, ch0, ch1);
            }
            // dump gh to sG[gate row][batch row]
#pragma unroll
            for (int nt = 0; nt < 3; nt++) {
                int c0 = nbase + nt * 8 + (lane & 3) * 2;
                int r0 = m_base + (lane >> 2);
                sG[c0 * PG + r0]           = acc[nt][0];
                sG[(c0 + 1) * PG + r0]     = acc[nt][1];
                sG[c0 * PG + r0 + 8]       = acc[nt][2];
                sG[(c0 + 1) * PG + r0 + 8] = acc[nt][3];
            }
        }
        __syncthreads();

        // gx ready for this step?
        if (rbuf == 0) { MBAR_WAIT(mb_g0, gxph0); gxph0 ^= 1; }
        else           { MBAR_WAIT(mb_g1, gxph1); gxph1 ^= 1; }

        // gate math
        const float* gxs = sGX + rbuf * 1536;
#pragma unroll
        for (int rep = 0; rep < 2; rep++) {
            int lb = lbase + rep * 16;
            float ghr = sG[jl * PG + lb];
            float ghz = sG[(16 + jl) * PG + lb];
            float ghn = sG[(32 + jl) * PG + lb];
            float gr = gxs[lb * 16 + jl];
            float gz = gxs[512 + lb * 16 + jl];
            float gn = gxs[1024 + lb * 16 + jl];
            int hidx = hkh * 8192 + lb * 256 + (((hjloc >> 3) ^ (lb & 7)) << 3) + (hjloc & 7);
            float hp = __bfloat162float(sHhi[hidx]) + __bfloat162float(sHlo[hidx]);
            float rr = 1.0f / (1.0f + __expf(-(gr + ghr + br)));
            float zz = 1.0f / (1.0f + __expf(-(gz + ghz + bz)));
            float xa = gn + rr * (ghn + bn);
            float e2 = __expf(2.0f * xa);
            float nn = 1.0f - __fdividef(2.0f, e2 + 1.0f);
            sX[lb * 16 + jl] = (1.0f - zz) * nn + zz * hp;
        }
        __syncthreads();

        // h_new global write (swizzled layout): one bf16x2 per array per thread
        {
            float v0 = sX[lb2 * 16 + jp];
            float v1 = sX[lb2 * 16 + jp + 1];
            __nv_bfloat16 h0 = __float2bfloat16(v0), h1 = __float2bfloat16(v1);
            __nv_bfloat162 hi01 = {h0, h1};
            __nv_bfloat162 lo01 = {__float2bfloat16(v0 - __bfloat162float(h0)),
                                   __float2bfloat16(v1 - __bfloat162float(h1))};
            *(__nv_bfloat162*)(wAhi + woff) = hi01;
            *(__nv_bfloat162*)(wAlo + woff) = lo01;
        }
        __syncthreads();

        // arrive at own sub-barrier (skip on last step)
        if (s != Tc - 1 && tid == 0) {
            __threadfence();
            asm volatile("fence.proxy.async;" ::: "memory");
            int old = atomicAdd(&g_bar_cnt[imine], 1);
            if (old == NHALF - 1) {
                g_bar_cnt[imine] = 0;
                __threadfence();
                g_bar_gen2[imine] = gbase_mine + s + 1;
            }
        }

        // off-critical-path: hs output (coalesced)
        {
            float2 xv = make_float2(sX[lb2 * 16 + jp], sX[lb2 * 16 + jp + 1]);
            *(float2*)&hs[((size_t)(b0 + lb2) * Tc + t) * (2 * Hc) + dir * Hc + j0 + jp] = xv;
        }
        // gx bulk prefetch for s+1
        if (s != Tc - 1 && tid == 0) {
            int tn = dir ? (Tc - 2 - s) : (s + 1);
            uint32_t mb = ((s + 1) & 1) ? mb_g1 : mb_g0;
            MBAR_EXPECT(mb, 6144u);
            BULK_G2S(uGX + ((s + 1) & 1) * 6144,
                     (const void*)(gxblk + (size_t)tn * 98304), 6144u, mb);
        }
    }

    __syncthreads();
    if (tid == 0) {
        MBAR_INVAL(mb_h0); MBAR_INVAL(mb_h1);
        MBAR_INVAL(mb_g0); MBAR_INVAL(mb_g1);
    }
}

// ---------------- copy final hidden states (de-swizzle) ----------------
__global__ void hy_copy_kernel(float* __restrict__ d_out, int layer) {
    int i = blockIdx.x * blockDim.x + threadIdx.x;   // 0..65535
    int dir = i >> 15;
    int rem = i & 32767;                              // = b*512 + j
    int b = rem >> 9;
    int j = rem & 511;
    int kh = j >> 8, jloc = j & 255;
    int off = ((dir * 2 + kh) * 64 + b) * 256 + ((((jloc >> 3) ^ (b & 7))) << 3) + (jloc & 7);
    d_out[HY_OFF + (size_t)(2 * layer + dir) * Bc * Hc + rem] =
        __bfloat162float(g_hAhi[0][off]) + __bfloat162float(g_hAlo[0][off]);
}

// ---------------- launch ----------------
extern "C" void kernel_launch(void* const* d_in, const int* in_sizes, int n_in,
                              void* d_out, int out_size)
{
    const float* xs    = (const float*)d_in[0];
    const float* w_ih0 = (const float*)d_in[1];
    const float* w_hh0 = (const float*)d_in[2];
    const float* b_ih0 = (const float*)d_in[3];
    const float* b_hh0 = (const float*)d_in[4];
    const float* w_ih1 = (const float*)d_in[5];
    const float* w_hh1 = (const float*)d_in[6];
    const float* b_ih1 = (const float*)d_in[7];
    const float* b_hh1 = (const float*)d_in[8];
    float* out = (float*)d_out;

    cudaFuncSetAttribute(gru_persist_mma,
                         cudaFuncAttributeMaxDynamicSharedMemorySize, PERSIST_SMEM);

    __nv_bfloat16 *xs_hi, *xs_lo, *h0_hi, *h0_lo, *w0_hi, *w0_lo, *w1_hi, *w1_lo;
    cudaGetSymbolAddress((void**)&xs_hi, g_xs_hi);
    cudaGetSymbolAddress((void**)&xs_lo, g_xs_lo);
    cudaGetSymbolAddress((void**)&h0_hi, g_h0_hi);
    cudaGetSymbolAddress((void**)&h0_lo, g_h0_lo);
    cudaGetSymbolAddress((void**)&w0_hi, g_w0_hi);
    cudaGetSymbolAddress((void**)&w0_lo, g_w0_lo);
    cudaGetSymbolAddress((void**)&w1_hi, g_w1_hi);
    cudaGetSymbolAddress((void**)&w1_lo, g_w1_lo);
    float* h0out;
    cudaGetSymbolAddress((void**)&h0out, g_h0out);

    dim3 gemm_grid(Gc / 128, M_TOK / 128, 2);   // (12, 256, 2)
    dim3 persist_grid(32, 2, 2);                // 128 blocks

    size_t n_w0 = (size_t)2 * Gc * Ec;
    size_t n_w1 = (size_t)2 * Gc * 2 * Hc;
    size_t n_xs = (size_t)M_TOK * Ec;
    size_t n_h0 = (size_t)M_TOK * 2 * Hc;

    split_bf16_kernel<<<(unsigned)((n_w0 + 255) / 256), 256>>>(w_ih0, w0_hi, w0_lo, n_w0);
    split_bf16_kernel<<<(unsigned)((n_w1 + 255) / 256), 256>>>(w_ih1, w1_hi, w1_lo, n_w1);
    split_bf16_kernel<<<(unsigned)((n_xs + 255) / 256), 256>>>(xs, xs_hi, xs_lo, n_xs);

    // ---- layer 0 ----
    gemm_mma<<<gemm_grid, 256>>>(xs_hi, xs_lo, w0_hi, w0_lo, b_ih0, Ec);
    zero_h_kernel<<<(2 * 2 * Bc * 256) / 256, 256>>>();
    gru_persist_mma<<<persist_grid, 256, PERSIST_SMEM>>>(w_hh0, b_hh0, out, 0);
    hy_copy_kernel<<<(2 * Bc * Hc) / 256, 256>>>(out, 0);

    // ---- layer 1 ----
    split_bf16_kernel<<<(unsigned)((n_h0 + 255) / 256), 256>>>(h0out, h0_hi, h0_lo, n_h0);
    gemm_mma<<<gemm_grid, 256>>>(h0_hi, h0_lo, w1_hi, w1_lo, b_ih1, 2 * Hc);
    zero_h_kernel<<<(2 * 2 * Bc * 256) / 256, 256>>>();
    gru_persist_mma<<<persist_grid, 256, PERSIST_SMEM>>>(w_hh1, b_hh1, out, 1);
    hy_copy_kernel<<<(2 * Bc * Hc) / 256, 256>>>(out, 1);
}